// round 1
// baseline (speedup 1.0000x reference)
#include <cuda_runtime.h>
#include <cuda_bf16.h>

#define NN 20000
#define NE 320000
#define NG 16
#define H1C 3
#define DC 128
#define F1C (H1C*DC)   // 384
#define NEG_SLOPE 0.2f

// ---------------- scratch (device globals; no allocation) ----------------
__device__ float    g_f1[NN*F1C];
__device__ float    g_el1[NN*H1C];
__device__ float    g_er1[NN*H1C];
__device__ unsigned g_m1[NN*H1C];
__device__ float    g_den1[NN*H1C];
__device__ float    g_e1[NE*H1C];
__device__ float    g_num1[NN*F1C];
__device__ float    g_h[NN*F1C];
__device__ float    g_f2[NN*DC];
__device__ float    g_el2[NN];
__device__ float    g_er2[NN];
__device__ unsigned g_m2[NN];
__device__ float    g_den2[NN];
__device__ float    g_e2[NE];
__device__ float    g_num2[NN*DC];
__device__ float    g_sums[NG*DC];
__device__ float    g_cnt[NG];

// monotonic float<->uint mapping for atomicMax on floats
__device__ __forceinline__ unsigned fflip(float f) {
    unsigned b = __float_as_uint(f);
    return (b & 0x80000000u) ? ~b : (b | 0x80000000u);
}
__device__ __forceinline__ float funflip(unsigned u) {
    return (u & 0x80000000u) ? __uint_as_float(u & 0x7FFFFFFFu) : __uint_as_float(~u);
}

// ---------------- zero-init all accumulators ----------------
__global__ void k_zero_all() {
    int i = blockIdx.x * blockDim.x + threadIdx.x;
    int stride = gridDim.x * blockDim.x;
    for (int j = i; j < NN*F1C; j += stride) g_num1[j] = 0.f;
    for (int j = i; j < NN*H1C; j += stride) { g_den1[j] = 0.f; g_m1[j] = 0u; }
    for (int j = i; j < NN*DC;  j += stride) g_num2[j] = 0.f;
    for (int j = i; j < NN;     j += stride) { g_den2[j] = 0.f; g_m2[j] = 0u; }
    for (int j = i; j < NG*DC;  j += stride) g_sums[j] = 0.f;
    for (int j = i; j < NG;     j += stride) g_cnt[j] = 0.f;
}

// ---------------- tiled SGEMM: C[M,N] = A[M,K] @ B[K,N] ----------------
// BM=BN=64, BK=16, 256 threads, 4x4 microtile. N % 64 == 0, K % 16 == 0.
__global__ void k_sgemm(const float* __restrict__ A, const float* __restrict__ B,
                        float* __restrict__ C, int M, int N, int K) {
    __shared__ float As[64][17];
    __shared__ float Bs[16][64];
    int tid = threadIdx.x;
    int tx = tid & 15, ty = tid >> 4;
    int rowBase = blockIdx.y * 64, colBase = blockIdx.x * 64;
    float acc[4][4] = {};
    for (int k0 = 0; k0 < K; k0 += 16) {
        #pragma unroll
        for (int l = 0; l < 4; l++) {
            int e = tid + l * 256;
            int r = e >> 4, c = e & 15;
            int gr = rowBase + r;
            As[r][c] = (gr < M) ? A[(long)gr * K + k0 + c] : 0.f;
        }
        #pragma unroll
        for (int l = 0; l < 4; l++) {
            int e = tid + l * 256;
            int r = e >> 6, c = e & 63;
            Bs[r][c] = B[(long)(k0 + r) * N + colBase + c];
        }
        __syncthreads();
        #pragma unroll
        for (int kk = 0; kk < 16; kk++) {
            float a[4], b[4];
            #pragma unroll
            for (int i = 0; i < 4; i++) a[i] = As[ty * 4 + i][kk];
            #pragma unroll
            for (int j = 0; j < 4; j++) b[j] = Bs[kk][tx * 4 + j];
            #pragma unroll
            for (int i = 0; i < 4; i++)
                #pragma unroll
                for (int j = 0; j < 4; j++)
                    acc[i][j] = fmaf(a[i], b[j], acc[i][j]);
        }
        __syncthreads();
    }
    #pragma unroll
    for (int i = 0; i < 4; i++) {
        int gr = rowBase + ty * 4 + i;
        if (gr < M) {
            #pragma unroll
            for (int j = 0; j < 4; j++)
                C[(long)gr * N + colBase + tx * 4 + j] = acc[i][j];
        }
    }
}

// ---------------- per-node attention scores: el/er = <f[n,h,:], al/ar[h,:]> ----------------
__global__ void k_scores(const float* __restrict__ f, const float* __restrict__ al,
                         const float* __restrict__ ar, float* __restrict__ el,
                         float* __restrict__ er, int nTasks, int H) {
    int gt = blockIdx.x * blockDim.x + threadIdx.x;
    int wid = gt >> 5;
    int lane = gt & 31;
    if (wid >= nTasks) return;
    int n = wid / H, h = wid - n * H;
    const float4* fp  = (const float4*)&f[(long)n * (H * DC) + h * DC];
    const float4* alp = (const float4*)&al[h * DC];
    const float4* arp = (const float4*)&ar[h * DC];
    float4 fv = fp[lane], a = alp[lane], r = arp[lane];
    float sl = fv.x * a.x + fv.y * a.y + fv.z * a.z + fv.w * a.w;
    float sr = fv.x * r.x + fv.y * r.y + fv.z * r.z + fv.w * r.w;
    #pragma unroll
    for (int o = 16; o > 0; o >>= 1) {
        sl += __shfl_xor_sync(0xFFFFFFFFu, sl, o);
        sr += __shfl_xor_sync(0xFFFFFFFFu, sr, o);
    }
    if (lane == 0) { el[wid] = sl; er[wid] = sr; }
}

// ---------------- edge pass 1: logits + segment max (atomicMax on flipped uint) ----------------
template <int H>
__global__ void k_edge_max(const int* __restrict__ src, const int* __restrict__ dst,
                           const float* __restrict__ el, const float* __restrict__ er,
                           float* __restrict__ elog, unsigned* __restrict__ m) {
    int e = blockIdx.x * blockDim.x + threadIdx.x;
    if (e >= NE) return;
    int s = src[e], d = dst[e];
    #pragma unroll
    for (int h = 0; h < H; h++) {
        float v = el[s * H + h] + er[d * H + h];
        v = v > 0.f ? v : NEG_SLOPE * v;
        elog[e * H + h] = v;
        atomicMax(&m[d * H + h], fflip(v));
    }
}

// ---------------- edge pass 2: ex = exp(e - m[dst]); denom += ex ----------------
template <int H>
__global__ void k_edge_exp(const int* __restrict__ dst, float* __restrict__ elog,
                           const unsigned* __restrict__ m, float* __restrict__ den) {
    int e = blockIdx.x * blockDim.x + threadIdx.x;
    if (e >= NE) return;
    int d = dst[e];
    #pragma unroll
    for (int h = 0; h < H; h++) {
        float mv = funflip(m[d * H + h]);
        float ex = __expf(elog[e * H + h] - mv);
        elog[e * H + h] = ex;
        atomicAdd(&den[d * H + h], ex);
    }
}

// ---------------- edge pass 3: num[dst,h,:] += ex * f[src,h,:]  (float4 gather) ----------------
template <int H>
__global__ void k_edge_agg(const int* __restrict__ src, const int* __restrict__ dst,
                           const float* __restrict__ elog, const float* __restrict__ f,
                           float* __restrict__ num) {
    int idx = blockIdx.x * blockDim.x + threadIdx.x;
    const int QP = H * 32;           // float4 chunks per edge
    if (idx >= NE * QP) return;
    int e = idx / QP;
    int r = idx - e * QP;
    int h = r >> 5;
    int q = r & 31;
    float ex = elog[e * H + h];
    int s = src[e], d = dst[e];
    float4 fv = *(const float4*)&f[(long)s * (H * DC) + h * DC + q * 4];
    float* o = &num[(long)d * (H * DC) + h * DC + q * 4];
    atomicAdd(o + 0, ex * fv.x);
    atomicAdd(o + 1, ex * fv.y);
    atomicAdd(o + 2, ex * fv.z);
    atomicAdd(o + 3, ex * fv.w);
}

// ---------------- layer-1 epilogue: h = elu(num/den + b1) ----------------
__global__ void k_final1(const float* __restrict__ b1) {
    int i = blockIdx.x * blockDim.x + threadIdx.x;
    if (i >= NN * F1C) return;
    int n = i / F1C;
    int j = i - n * F1C;
    int h = j >> 7;
    float den = g_den1[n * H1C + h];
    den = den > 0.f ? den : 1.f;
    float v = g_num1[i] / den + b1[j];
    g_h[i] = v > 0.f ? v : expm1f(v);
}

// ---------------- layer-2 epilogue fused with graph mean-pool accumulation ----------------
__global__ void k_final2_pool(const float* __restrict__ b2, const int* __restrict__ gids) {
    int i = blockIdx.x * blockDim.x + threadIdx.x;
    if (i >= NN * DC) return;
    int n = i >> 7;
    int j = i & 127;
    float den = g_den2[n];
    den = den > 0.f ? den : 1.f;
    float v = g_num2[i] / den + b2[j];
    int g = gids[n];
    atomicAdd(&g_sums[g * DC + j], v);
    if (j == 0) atomicAdd(&g_cnt[g], 1.f);
}

// ---------------- output: relu((sums/cnt) @ linW + linb) ----------------
__global__ void k_out(const float* __restrict__ linW, const float* __restrict__ linb,
                      float* __restrict__ out) {
    int g = blockIdx.x;
    int c = threadIdx.x;
    __shared__ float hg[DC];
    float cnt = g_cnt[g];
    if (cnt < 1.f) cnt = 1.f;
    hg[c] = g_sums[g * DC + c] / cnt;
    __syncthreads();
    float acc = linb[c];
    #pragma unroll 8
    for (int k = 0; k < DC; k++)
        acc = fmaf(hg[k], linW[k * DC + c], acc);
    out[g * DC + c] = acc > 0.f ? acc : 0.f;
}

// ---------------- launch ----------------
extern "C" void kernel_launch(void* const* d_in, const int* in_sizes, int n_in,
                              void* d_out, int out_size) {
    const float* x    = (const float*)d_in[0];
    const int*   src  = (const int*)  d_in[1];
    const int*   dst  = (const int*)  d_in[2];
    const int*   gids = (const int*)  d_in[3];
    const float* W1   = (const float*)d_in[4];
    const float* al1  = (const float*)d_in[5];
    const float* ar1  = (const float*)d_in[6];
    const float* b1   = (const float*)d_in[7];
    const float* W2   = (const float*)d_in[8];
    const float* al2  = (const float*)d_in[9];
    const float* ar2  = (const float*)d_in[10];
    const float* b2   = (const float*)d_in[11];
    const float* linW = (const float*)d_in[12];
    const float* linb = (const float*)d_in[13];
    float* out = (float*)d_out;

    void *p_f1, *p_el1, *p_er1, *p_m1, *p_den1, *p_e1, *p_num1, *p_h;
    void *p_f2, *p_el2, *p_er2, *p_m2, *p_den2, *p_e2, *p_num2;
    cudaGetSymbolAddress(&p_f1,   g_f1);
    cudaGetSymbolAddress(&p_el1,  g_el1);
    cudaGetSymbolAddress(&p_er1,  g_er1);
    cudaGetSymbolAddress(&p_m1,   g_m1);
    cudaGetSymbolAddress(&p_den1, g_den1);
    cudaGetSymbolAddress(&p_e1,   g_e1);
    cudaGetSymbolAddress(&p_num1, g_num1);
    cudaGetSymbolAddress(&p_h,    g_h);
    cudaGetSymbolAddress(&p_f2,   g_f2);
    cudaGetSymbolAddress(&p_el2,  g_el2);
    cudaGetSymbolAddress(&p_er2,  g_er2);
    cudaGetSymbolAddress(&p_m2,   g_m2);
    cudaGetSymbolAddress(&p_den2, g_den2);
    cudaGetSymbolAddress(&p_e2,   g_e2);
    cudaGetSymbolAddress(&p_num2, g_num2);

    // 0) zero accumulators
    k_zero_all<<<2048, 256>>>();

    // ---- Layer 1 ----
    {
        dim3 grid(F1C / 64, (NN + 63) / 64);
        k_sgemm<<<grid, 256>>>(x, W1, (float*)p_f1, NN, F1C, 128);
    }
    {
        int tasks = NN * H1C;
        int blocks = (tasks * 32 + 255) / 256;
        k_scores<<<blocks, 256>>>((const float*)p_f1, al1, ar1,
                                  (float*)p_el1, (float*)p_er1, tasks, H1C);
    }
    k_edge_max<H1C><<<(NE + 255) / 256, 256>>>(src, dst, (const float*)p_el1,
                                               (const float*)p_er1, (float*)p_e1,
                                               (unsigned*)p_m1);
    k_edge_exp<H1C><<<(NE + 255) / 256, 256>>>(dst, (float*)p_e1,
                                               (const unsigned*)p_m1, (float*)p_den1);
    {
        int total = NE * H1C * 32;
        k_edge_agg<H1C><<<(total + 255) / 256, 256>>>(src, dst, (const float*)p_e1,
                                                      (const float*)p_f1, (float*)p_num1);
    }
    k_final1<<<(NN * F1C + 255) / 256, 256>>>(b1);

    // ---- Layer 2 ----
    {
        dim3 grid(DC / 64, (NN + 63) / 64);
        k_sgemm<<<grid, 256>>>((const float*)p_h, W2, (float*)p_f2, NN, DC, F1C);
    }
    {
        int tasks = NN;
        int blocks = (tasks * 32 + 255) / 256;
        k_scores<<<blocks, 256>>>((const float*)p_f2, al2, ar2,
                                  (float*)p_el2, (float*)p_er2, tasks, 1);
    }
    k_edge_max<1><<<(NE + 255) / 256, 256>>>(src, dst, (const float*)p_el2,
                                             (const float*)p_er2, (float*)p_e2,
                                             (unsigned*)p_m2);
    k_edge_exp<1><<<(NE + 255) / 256, 256>>>(dst, (float*)p_e2,
                                             (const unsigned*)p_m2, (float*)p_den2);
    {
        int total = NE * 32;
        k_edge_agg<1><<<(total + 255) / 256, 256>>>(src, dst, (const float*)p_e2,
                                                    (const float*)p_f2, (float*)p_num2);
    }
    k_final2_pool<<<(NN * DC + 255) / 256, 256>>>(b2, gids);

    // ---- readout ----
    k_out<<<NG, DC>>>(linW, linb, out);
}

// round 2
// speedup vs baseline: 3.0281x; 3.0281x over previous
#include <cuda_runtime.h>
#include <cuda_bf16.h>

#define NN 20000
#define NE 320000
#define NG 16
#define H1C 3
#define DC 128
#define F1C (H1C*DC)   // 384
#define NEG_SLOPE 0.2f

typedef unsigned long long ull;

// ---------------- scratch (device globals; no allocation) ----------------
__device__ float g_f1[NN*F1C];     // projected features layer1
__device__ float g_el1[NN*H1C];
__device__ float g_er1[NN*H1C];
__device__ float g_h[NN*F1C];      // elu output of layer1
__device__ float g_f2[NN*DC];
__device__ float g_el2[NN];
__device__ float g_er2[NN];
__device__ float g_h2[NN*DC];      // layer2 node output
__device__ int   g_deg[NN];
__device__ int   g_cur[NN];
__device__ int   g_off[NN+1];
__device__ int   g_csr_src[NE];    // src node per CSR slot (grouped by dst)
__device__ float g_sums[NG*DC];
__device__ float g_cnt[NG];

// ---------------- small zero init ----------------
__global__ void k_zero_small() {
    int i = blockIdx.x * blockDim.x + threadIdx.x;
    if (i < NN) { g_deg[i] = 0; g_cur[i] = 0; }
    if (i < NG*DC) g_sums[i] = 0.f;
    if (i < NG) g_cnt[i] = 0.f;
}

// ---------------- CSR build ----------------
__global__ void k_deg(const int* __restrict__ dst) {
    int i = blockIdx.x * blockDim.x + threadIdx.x;
    if (i < NE) atomicAdd(&g_deg[dst[i]], 1);
}

// single block, 256 threads: exclusive scan of g_deg -> g_off
__global__ void k_scan() {
    __shared__ int partial[256];
    int tid = threadIdx.x;
    const int CH = (NN + 255) / 256;   // 79
    int b0 = tid * CH;
    int s = 0;
    for (int i = 0; i < CH; i++) {
        int n = b0 + i;
        if (n < NN) s += g_deg[n];
    }
    partial[tid] = s;
    __syncthreads();
    if (tid == 0) {
        int c = 0;
        for (int i = 0; i < 256; i++) { int t = partial[i]; partial[i] = c; c += t; }
        g_off[NN] = c;
    }
    __syncthreads();
    int run = partial[tid];
    for (int i = 0; i < CH; i++) {
        int n = b0 + i;
        if (n < NN) { g_off[n] = run; run += g_deg[n]; }
    }
}

__global__ void k_scatter(const int* __restrict__ src, const int* __restrict__ dst) {
    int i = blockIdx.x * blockDim.x + threadIdx.x;
    if (i >= NE) return;
    int d = dst[i];
    int p = atomicAdd(&g_cur[d], 1);
    g_csr_src[g_off[d] + p] = src[i];
}

// ---------------- FFMA2 helpers ----------------
__device__ __forceinline__ void ffma2(ull &d, ull a, ull b) {
    asm("fma.rn.f32x2 %0, %1, %2, %0;" : "+l"(d) : "l"(a), "l"(b));
}
__device__ __forceinline__ ull pack2(float x) {
    ull r;
    asm("mov.b64 %0, {%1, %1};" : "=l"(r) : "f"(x));
    return r;
}

// ---------------- SGEMM with packed f32x2 FMA ----------------
// C[M,N] = A[M,K] @ B[K,N]; BM=BN=128, BK=8, 256 threads, 8x8 microtile.
// Requires N % 128 == 0, K % 8 == 0. M arbitrary (row bounds checked).
__global__ void __launch_bounds__(256, 2)
k_gemm(const float* __restrict__ A, const float* __restrict__ B,
       float* __restrict__ C, int M, int N, int K) {
    __shared__ float As[8][128];   // transposed: As[k][m]
    __shared__ float Bs[8][128];
    int tid = threadIdx.x;
    int m0 = blockIdx.y * 128, n0 = blockIdx.x * 128;
    int arow = tid >> 1, ac4 = (tid & 1) * 4;
    int brow = tid >> 5, bc4 = (tid & 31) * 4;
    int tm = (tid >> 4) * 8, tn = (tid & 15) * 8;

    ull acc[8][4];
    #pragma unroll
    for (int i = 0; i < 8; i++)
        #pragma unroll
        for (int j = 0; j < 4; j++) acc[i][j] = 0ull;

    bool avalid = (m0 + arow) < M;
    const float* Aptr = A + (size_t)(m0 + arow) * K + ac4;
    const float* Bptr = B + (size_t)brow * N + n0 + bc4;

    for (int k0 = 0; k0 < K; k0 += 8) {
        float4 av = avalid ? *(const float4*)(Aptr + k0) : make_float4(0.f,0.f,0.f,0.f);
        As[ac4 + 0][arow] = av.x;
        As[ac4 + 1][arow] = av.y;
        As[ac4 + 2][arow] = av.z;
        As[ac4 + 3][arow] = av.w;
        float4 bv = *(const float4*)(Bptr + (size_t)k0 * N);
        *(float4*)&Bs[brow][bc4] = bv;
        __syncthreads();
        #pragma unroll
        for (int kk = 0; kk < 8; kk++) {
            float4 a0 = *(const float4*)&As[kk][tm];
            float4 a1 = *(const float4*)&As[kk][tm + 4];
            ulonglong2 u0 = *(const ulonglong2*)&Bs[kk][tn];
            ulonglong2 u1 = *(const ulonglong2*)&Bs[kk][tn + 4];
            ull aa[8];
            aa[0] = pack2(a0.x); aa[1] = pack2(a0.y);
            aa[2] = pack2(a0.z); aa[3] = pack2(a0.w);
            aa[4] = pack2(a1.x); aa[5] = pack2(a1.y);
            aa[6] = pack2(a1.z); aa[7] = pack2(a1.w);
            #pragma unroll
            for (int i = 0; i < 8; i++) {
                ffma2(acc[i][0], aa[i], u0.x);
                ffma2(acc[i][1], aa[i], u0.y);
                ffma2(acc[i][2], aa[i], u1.x);
                ffma2(acc[i][3], aa[i], u1.y);
            }
        }
        __syncthreads();
    }
    #pragma unroll
    for (int i = 0; i < 8; i++) {
        int gr = m0 + tm + i;
        if (gr < M) {
            float2 f0 = *(float2*)&acc[i][0];
            float2 f1 = *(float2*)&acc[i][1];
            float2 f2 = *(float2*)&acc[i][2];
            float2 f3 = *(float2*)&acc[i][3];
            *(float4*)&C[(size_t)gr * N + n0 + tn]     = make_float4(f0.x, f0.y, f1.x, f1.y);
            *(float4*)&C[(size_t)gr * N + n0 + tn + 4] = make_float4(f2.x, f2.y, f3.x, f3.y);
        }
    }
}

// ---------------- per-node attention scores ----------------
__global__ void k_scores(const float* __restrict__ f, const float* __restrict__ al,
                         const float* __restrict__ ar, float* __restrict__ el,
                         float* __restrict__ er, int nTasks, int H) {
    int gt = blockIdx.x * blockDim.x + threadIdx.x;
    int wid = gt >> 5;
    int lane = gt & 31;
    if (wid >= nTasks) return;
    int n = wid / H, h = wid - n * H;
    const float4* fp  = (const float4*)&f[(size_t)n * (H * DC) + h * DC];
    const float4* alp = (const float4*)&al[h * DC];
    const float4* arp = (const float4*)&ar[h * DC];
    float4 fv = fp[lane], a = alp[lane], r = arp[lane];
    float sl = fv.x * a.x + fv.y * a.y + fv.z * a.z + fv.w * a.w;
    float sr = fv.x * r.x + fv.y * r.y + fv.z * r.z + fv.w * r.w;
    #pragma unroll
    for (int o = 16; o > 0; o >>= 1) {
        sl += __shfl_xor_sync(0xFFFFFFFFu, sl, o);
        sr += __shfl_xor_sync(0xFFFFFFFFu, sr, o);
    }
    if (lane == 0) { el[wid] = sl; er[wid] = sr; }
}

// ---------------- fused softmax + aggregation: one warp per (dst, head) ----------------
// pass1: segment max over incoming edges; pass2: exp, denom, weighted gather-sum.
// Epilogue applies bias and (optional) ELU, writes final node features.
template <int H, bool ELU>
__global__ void k_agg(const float* __restrict__ f, const float* __restrict__ el,
                      const float* __restrict__ er, const float* __restrict__ b,
                      float* __restrict__ out) {
    int w = (blockIdx.x * blockDim.x + threadIdx.x) >> 5;
    int lane = threadIdx.x & 31;
    if (w >= NN * H) return;
    int d = w / H, h = w - d * H;
    int off0 = g_off[d];
    int deg = g_off[d + 1] - off0;
    float erd = er[d * H + h];

    // pass 1: max
    float mx = -3.0e38f;
    for (int j = lane; j < deg; j += 32) {
        int s = g_csr_src[off0 + j];
        float v = el[s * H + h] + erd;
        v = v > 0.f ? v : NEG_SLOPE * v;
        mx = fmaxf(mx, v);
    }
    #pragma unroll
    for (int o = 16; o > 0; o >>= 1)
        mx = fmaxf(mx, __shfl_xor_sync(0xFFFFFFFFu, mx, o));

    // pass 2: exp + denom + weighted feature accumulation
    float4 acc = make_float4(0.f, 0.f, 0.f, 0.f);
    float den = 0.f;
    for (int j = 0; j < deg; j++) {
        int s = g_csr_src[off0 + j];                 // broadcast load
        float v = el[s * H + h] + erd;
        v = v > 0.f ? v : NEG_SLOPE * v;
        float ex = __expf(v - mx);
        den += ex;                                    // identical in all lanes
        float4 fv = *(const float4*)&f[(size_t)s * (H * DC) + h * DC + lane * 4];
        acc.x = fmaf(ex, fv.x, acc.x);
        acc.y = fmaf(ex, fv.y, acc.y);
        acc.z = fmaf(ex, fv.z, acc.z);
        acc.w = fmaf(ex, fv.w, acc.w);
    }
    float inv = 1.f / (den > 0.f ? den : 1.f);
    float4 bb = *(const float4*)&b[h * DC + lane * 4];
    float4 r;
    r.x = acc.x * inv + bb.x;
    r.y = acc.y * inv + bb.y;
    r.z = acc.z * inv + bb.z;
    r.w = acc.w * inv + bb.w;
    if (ELU) {
        r.x = r.x > 0.f ? r.x : expm1f(r.x);
        r.y = r.y > 0.f ? r.y : expm1f(r.y);
        r.z = r.z > 0.f ? r.z : expm1f(r.z);
        r.w = r.w > 0.f ? r.w : expm1f(r.w);
    }
    *(float4*)&out[(size_t)d * (H * DC) + h * DC + lane * 4] = r;
}

// ---------------- graph mean pool (graph_ids sorted) ----------------
__global__ void k_pool(const float* __restrict__ h2, const int* __restrict__ gids) {
    __shared__ float sacc[NG][DC];
    __shared__ float scnt[NG];
    int tid = threadIdx.x;   // 128
    #pragma unroll
    for (int g = 0; g < NG; g++) sacc[g][tid] = 0.f;
    if (tid < NG) scnt[tid] = 0.f;
    __syncthreads();
    int per = (NN + gridDim.x - 1) / gridDim.x;
    int n0 = blockIdx.x * per;
    int n1 = n0 + per; if (n1 > NN) n1 = NN;
    int curg = -1; float racc = 0.f; float rcnt = 0.f;
    for (int n = n0; n < n1; n++) {
        int g = gids[n];
        if (g != curg) {
            if (curg >= 0) {
                sacc[curg][tid] += racc;
                if (tid == 0) scnt[curg] += rcnt;
            }
            curg = g; racc = 0.f; rcnt = 0.f;
        }
        racc += h2[(size_t)n * DC + tid];
        rcnt += 1.f;
    }
    if (curg >= 0) {
        sacc[curg][tid] += racc;
        if (tid == 0) scnt[curg] += rcnt;
    }
    __syncthreads();
    #pragma unroll
    for (int g = 0; g < NG; g++) atomicAdd(&g_sums[g * DC + tid], sacc[g][tid]);
    if (tid < NG) atomicAdd(&g_cnt[tid], scnt[tid]);
}

// ---------------- output: relu((sums/cnt) @ linW + linb) ----------------
__global__ void k_out(const float* __restrict__ linW, const float* __restrict__ linb,
                      float* __restrict__ out) {
    int g = blockIdx.x;
    int c = threadIdx.x;
    __shared__ float hg[DC];
    float cnt = g_cnt[g];
    if (cnt < 1.f) cnt = 1.f;
    hg[c] = g_sums[g * DC + c] / cnt;
    __syncthreads();
    float acc = linb[c];
    #pragma unroll 8
    for (int k = 0; k < DC; k++)
        acc = fmaf(hg[k], linW[k * DC + c], acc);
    out[g * DC + c] = acc > 0.f ? acc : 0.f;
}

// ---------------- launch ----------------
extern "C" void kernel_launch(void* const* d_in, const int* in_sizes, int n_in,
                              void* d_out, int out_size) {
    const float* x    = (const float*)d_in[0];
    const int*   src  = (const int*)  d_in[1];
    const int*   dst  = (const int*)  d_in[2];
    const int*   gids = (const int*)  d_in[3];
    const float* W1   = (const float*)d_in[4];
    const float* al1  = (const float*)d_in[5];
    const float* ar1  = (const float*)d_in[6];
    const float* b1   = (const float*)d_in[7];
    const float* W2   = (const float*)d_in[8];
    const float* al2  = (const float*)d_in[9];
    const float* ar2  = (const float*)d_in[10];
    const float* b2   = (const float*)d_in[11];
    const float* linW = (const float*)d_in[12];
    const float* linb = (const float*)d_in[13];
    float* out = (float*)d_out;

    void *p_f1, *p_el1, *p_er1, *p_h, *p_f2, *p_el2, *p_er2, *p_h2;
    cudaGetSymbolAddress(&p_f1,  g_f1);
    cudaGetSymbolAddress(&p_el1, g_el1);
    cudaGetSymbolAddress(&p_er1, g_er1);
    cudaGetSymbolAddress(&p_h,   g_h);
    cudaGetSymbolAddress(&p_f2,  g_f2);
    cudaGetSymbolAddress(&p_el2, g_el2);
    cudaGetSymbolAddress(&p_er2, g_er2);
    cudaGetSymbolAddress(&p_h2,  g_h2);

    // 0) small zero + CSR build (shared by both layers)
    k_zero_small<<<(NN + 255) / 256, 256>>>();
    k_deg<<<(NE + 255) / 256, 256>>>(dst);
    k_scan<<<1, 256>>>();
    k_scatter<<<(NE + 255) / 256, 256>>>(src, dst);

    // ---- Layer 1 ----
    {
        dim3 grid(F1C / 128, (NN + 127) / 128);
        k_gemm<<<grid, 256>>>(x, W1, (float*)p_f1, NN, F1C, 128);
    }
    {
        int tasks = NN * H1C;
        k_scores<<<(tasks * 32 + 255) / 256, 256>>>((const float*)p_f1, al1, ar1,
                                                    (float*)p_el1, (float*)p_er1, tasks, H1C);
    }
    {
        int warps = NN * H1C;
        k_agg<H1C, true><<<(warps * 32 + 255) / 256, 256>>>(
            (const float*)p_f1, (const float*)p_el1, (const float*)p_er1, b1, (float*)p_h);
    }

    // ---- Layer 2 ----
    {
        dim3 grid(DC / 128, (NN + 127) / 128);
        k_gemm<<<grid, 256>>>((const float*)p_h, W2, (float*)p_f2, NN, DC, F1C);
    }
    {
        int tasks = NN;
        k_scores<<<(tasks * 32 + 255) / 256, 256>>>((const float*)p_f2, al2, ar2,
                                                    (float*)p_el2, (float*)p_er2, tasks, 1);
    }
    {
        int warps = NN;
        k_agg<1, false><<<(warps * 32 + 255) / 256, 256>>>(
            (const float*)p_f2, (const float*)p_el2, (const float*)p_er2, b2, (float*)p_h2);
    }

    // ---- pool + readout ----
    k_pool<<<64, DC>>>((const float*)p_h2, gids);
    k_out<<<NG, DC>>>(linW, linb, out);
}

// round 4
// speedup vs baseline: 3.4071x; 1.1252x over previous
#include <cuda_runtime.h>
#include <cuda_bf16.h>
#include <cstdint>

#define NN 20000
#define NE 320000
#define NG 16
#define H1C 3
#define DC 128
#define F1C (H1C*DC)   // 384
#define NEG_SLOPE 0.2f

// ---------------- scratch (device globals; no allocation) ----------------
__device__ float          g_f1[NN*F1C];
__device__ float          g_el1[NN*H1C];
__device__ float          g_er1[NN*H1C];
__device__ __nv_bfloat16  g_xhi[NN*DC];
__device__ __nv_bfloat16  g_xlo[NN*DC];
__device__ __nv_bfloat16  g_hhi[NN*F1C];
__device__ __nv_bfloat16  g_hlo[NN*F1C];
__device__ __nv_bfloat16  g_w1t_hi[F1C*DC];   // [384][128] = W1^T
__device__ __nv_bfloat16  g_w1t_lo[F1C*DC];
__device__ __nv_bfloat16  g_w2t_hi[DC*F1C];   // [128][384] = W2^T
__device__ __nv_bfloat16  g_w2t_lo[DC*F1C];
__device__ float          g_f2[NN*DC];
__device__ float          g_el2[NN];
__device__ float          g_er2[NN];
__device__ float          g_h2[NN*DC];
__device__ int            g_deg[NN];
__device__ int            g_cur[NN];
__device__ int            g_off[NN+1];
__device__ int            g_csr_src[NE];
__device__ float          g_sums[NG*DC];
__device__ float          g_cnt[NG];

// ---------------- helpers ----------------
__device__ __forceinline__ uint32_t smem_u32(const void* p) {
    uint32_t a;
    asm("{ .reg .u64 t; cvta.to.shared.u64 t, %1; cvt.u32.u64 %0, t; }" : "=r"(a) : "l"(p));
    return a;
}
__device__ __forceinline__ void mma16816(float* c, const uint32_t* a, const uint32_t* b) {
    asm volatile(
        "mma.sync.aligned.m16n8k16.row.col.f32.bf16.bf16.f32 "
        "{%0,%1,%2,%3}, {%4,%5,%6,%7}, {%8,%9}, {%0,%1,%2,%3};"
        : "+f"(c[0]), "+f"(c[1]), "+f"(c[2]), "+f"(c[3])
        : "r"(a[0]), "r"(a[1]), "r"(a[2]), "r"(a[3]), "r"(b[0]), "r"(b[1]));
}
__device__ __forceinline__ void ldsm4(uint32_t* d, uint32_t addr) {
    asm volatile("ldmatrix.sync.aligned.m8n8.x4.shared.b16 {%0,%1,%2,%3}, [%4];"
                 : "=r"(d[0]), "=r"(d[1]), "=r"(d[2]), "=r"(d[3]) : "r"(addr));
}

// smem byte offsets for the GEMM (row stride 80B = 40 bf16)
#define SA_HI 0
#define SA_LO 10240
#define SB_HI 20480
#define SB_LO 30720
#define SM_GEMM 40960

// ---------------- small zero init ----------------
__global__ void k_zero_small() {
    int i = blockIdx.x * blockDim.x + threadIdx.x;
    if (i < NN) { g_deg[i] = 0; g_cur[i] = 0; }
    if (i < NG*DC) g_sums[i] = 0.f;
    if (i < NG) g_cnt[i] = 0.f;
}

// ---------------- CSR build ----------------
__global__ void k_deg(const int* __restrict__ dst) {
    int i = blockIdx.x * blockDim.x + threadIdx.x;
    if (i < NE) atomicAdd(&g_deg[dst[i]], 1);
}
__global__ void k_scan() {
    __shared__ int partial[256];
    int tid = threadIdx.x;
    const int CH = (NN + 255) / 256;
    int b0 = tid * CH;
    int s = 0;
    for (int i = 0; i < CH; i++) { int n = b0 + i; if (n < NN) s += g_deg[n]; }
    partial[tid] = s;
    __syncthreads();
    if (tid == 0) {
        int c = 0;
        for (int i = 0; i < 256; i++) { int t = partial[i]; partial[i] = c; c += t; }
        g_off[NN] = c;
    }
    __syncthreads();
    int run = partial[tid];
    for (int i = 0; i < CH; i++) {
        int n = b0 + i;
        if (n < NN) { g_off[n] = run; run += g_deg[n]; }
    }
}
__global__ void k_scatter(const int* __restrict__ src, const int* __restrict__ dst) {
    int i = blockIdx.x * blockDim.x + threadIdx.x;
    if (i >= NE) return;
    int d = dst[i];
    int p = atomicAdd(&g_cur[d], 1);
    g_csr_src[g_off[d] + p] = src[i];
}

// ---------------- fp32 -> bf16 hi/lo split ----------------
__global__ void k_split(const float* __restrict__ A, __nv_bfloat16* __restrict__ hi,
                        __nv_bfloat16* __restrict__ lo, int n) {
    int i = 4 * (blockIdx.x * blockDim.x + threadIdx.x);
    if (i >= n) return;
    float4 v = *(const float4*)&A[i];
    __nv_bfloat16 h0 = __float2bfloat16(v.x), h1 = __float2bfloat16(v.y);
    __nv_bfloat16 h2 = __float2bfloat16(v.z), h3 = __float2bfloat16(v.w);
    __nv_bfloat16 l0 = __float2bfloat16(v.x - __bfloat162float(h0));
    __nv_bfloat16 l1 = __float2bfloat16(v.y - __bfloat162float(h1));
    __nv_bfloat16 l2 = __float2bfloat16(v.z - __bfloat162float(h2));
    __nv_bfloat16 l3 = __float2bfloat16(v.w - __bfloat162float(h3));
    *(__nv_bfloat162*)&hi[i]     = __halves2bfloat162(h0, h1);
    *(__nv_bfloat162*)&hi[i + 2] = __halves2bfloat162(h2, h3);
    *(__nv_bfloat162*)&lo[i]     = __halves2bfloat162(l0, l1);
    *(__nv_bfloat162*)&lo[i + 2] = __halves2bfloat162(l2, l3);
}

// ---------------- W [K,N] -> W^T [N,K] bf16 hi/lo ----------------
__global__ void k_tsplit(const float* __restrict__ W, __nv_bfloat16* __restrict__ hi,
                         __nv_bfloat16* __restrict__ lo, int K, int N) {
    int i = blockIdx.x * blockDim.x + threadIdx.x;
    if (i >= N * K) return;
    int n = i / K, k = i - n * K;
    float x = W[(size_t)k * N + n];
    __nv_bfloat16 h = __float2bfloat16(x);
    hi[i] = h;
    lo[i] = __float2bfloat16(x - __bfloat162float(h));
}

// ---------------- HMMA split-bf16 GEMM + fused attention scores ----------------
// C[M,N] = A[M,K] @ B^T, B stored [N,K]. A,B pre-split bf16 hi/lo.
// Block 128x128, BK=32, 8 warps (2M x 4N), warp tile 64x32, mma.m16n8k16.
// Fused epilogue: el[n,h]=dot(C_row,al[h]), er likewise (h = blockIdx.x).
__global__ void __launch_bounds__(256, 1)
k_gemm_mma(const __nv_bfloat16* __restrict__ Ahi, const __nv_bfloat16* __restrict__ Alo,
           const __nv_bfloat16* __restrict__ Bhi, const __nv_bfloat16* __restrict__ Blo,
           float* __restrict__ C, const float* __restrict__ al, const float* __restrict__ ar,
           float* __restrict__ el, float* __restrict__ er, int M, int N, int K, int H) {
    extern __shared__ char smem[];
    uint32_t sb = smem_u32(smem);
    int tid = threadIdx.x;
    int wid = tid >> 5, lane = tid & 31;
    int wm = wid >> 2, wn = wid & 3;
    int m0 = blockIdx.y * 128, n0 = blockIdx.x * 128;
    int h = blockIdx.x;

    float acc[4][4][4];
    #pragma unroll
    for (int i = 0; i < 4; i++)
        #pragma unroll
        for (int j = 0; j < 4; j++)
            #pragma unroll
            for (int q = 0; q < 4; q++) acc[i][j][q] = 0.f;

    int lr = tid >> 2, cq = tid & 3;            // tile-load role
    // ldmatrix per-lane addresses (byte offsets within a buffer)
    int a_row = wm * 64 + (lane & 15);
    int a_coff = (lane >> 4) * 16;              // bytes: +8 bf16 for mats 2,3
    int b_row = wn * 32 + (lane & 7) + ((lane >> 4) & 1) * 8;
    int b_coff = ((lane >> 3) & 1) * 16;

    for (int k0 = 0; k0 < K; k0 += 32) {
        __syncthreads();
        #pragma unroll
        for (int half = 0; half < 2; half++) {
            int rr = lr + half * 64;
            uint32_t off = rr * 80 + cq * 16;
            int gm = m0 + rr;
            uint4 vh = make_uint4(0u,0u,0u,0u), vl = make_uint4(0u,0u,0u,0u);
            if (gm < M) {
                vh = *(const uint4*)&Ahi[(size_t)gm * K + k0 + cq * 8];
                vl = *(const uint4*)&Alo[(size_t)gm * K + k0 + cq * 8];
            }
            *(uint4*)(smem + SA_HI + off) = vh;
            *(uint4*)(smem + SA_LO + off) = vl;
            uint4 wh = *(const uint4*)&Bhi[(size_t)(n0 + rr) * K + k0 + cq * 8];
            uint4 wl = *(const uint4*)&Blo[(size_t)(n0 + rr) * K + k0 + cq * 8];
            *(uint4*)(smem + SB_HI + off) = wh;
            *(uint4*)(smem + SB_LO + off) = wl;
        }
        __syncthreads();
        #pragma unroll
        for (int ks = 0; ks < 2; ks++) {
            uint32_t kb = ks * 32;              // 16 bf16 = 32B
            uint32_t ahi[4][4], alo[4][4];
            #pragma unroll
            for (int mf = 0; mf < 4; mf++) {
                uint32_t ao = (a_row + mf * 16) * 80 + kb + a_coff;
                ldsm4(ahi[mf], sb + SA_HI + ao);
                ldsm4(alo[mf], sb + SA_LO + ao);
            }
            uint32_t bhi[4][4], blo[4][4];      // [2 loads][4 regs] -> frags
            #pragma unroll
            for (int j = 0; j < 2; j++) {
                uint32_t bo = (b_row + j * 16) * 80 + kb + b_coff;
                ldsm4(bhi[j * 2], sb + SB_HI + bo);   // regs 0,1 -> frag 2j; 2,3 -> 2j+1
                ldsm4(blo[j * 2], sb + SB_LO + bo);
            }
            #pragma unroll
            for (int mf = 0; mf < 4; mf++) {
                #pragma unroll
                for (int nf = 0; nf < 4; nf++) {
                    const uint32_t* bh = &bhi[(nf >> 1) * 2][(nf & 1) * 2];
                    const uint32_t* bl = &blo[(nf >> 1) * 2][(nf & 1) * 2];
                    mma16816(acc[mf][nf], ahi[mf], bh);
                    mma16816(acc[mf][nf], ahi[mf], bl);
                    mma16816(acc[mf][nf], alo[mf], bh);
                }
            }
        }
    }
    __syncthreads();

    // ---- fused el/er: accumulate per-row dot partials into smem ----
    float* el_s = (float*)(smem + 16896);
    float* er_s = el_s + 128;
    if (tid < 128) { el_s[tid] = 0.f; er_s[tid] = 0.f; }
    __syncthreads();
    {
        float a0[4], a1[4], r0[4], r1[4];
        #pragma unroll
        for (int nf = 0; nf < 4; nf++) {
            int gc = h * DC + wn * 32 + nf * 8 + (lane & 3) * 2;
            a0[nf] = al[gc]; a1[nf] = al[gc + 1];
            r0[nf] = ar[gc]; r1[nf] = ar[gc + 1];
        }
        #pragma unroll
        for (int mf = 0; mf < 4; mf++) {
            float s0e = 0.f, s0r = 0.f, s1e = 0.f, s1r = 0.f;
            #pragma unroll
            for (int nf = 0; nf < 4; nf++) {
                s0e += acc[mf][nf][0] * a0[nf] + acc[mf][nf][1] * a1[nf];
                s0r += acc[mf][nf][0] * r0[nf] + acc[mf][nf][1] * r1[nf];
                s1e += acc[mf][nf][2] * a0[nf] + acc[mf][nf][3] * a1[nf];
                s1r += acc[mf][nf][2] * r0[nf] + acc[mf][nf][3] * r1[nf];
            }
            int row = wm * 64 + mf * 16 + (lane >> 2);
            atomicAdd(&el_s[row], s0e);
            atomicAdd(&er_s[row], s0r);
            atomicAdd(&el_s[row + 8], s1e);
            atomicAdd(&er_s[row + 8], s1r);
        }
    }

    // ---- staged C store: 4 chunks of 32 cols ----
    float* stage = (float*)smem;   // [128][33]
    #pragma unroll
    for (int cb = 0; cb < 4; cb++) {
        __syncthreads();
        if (wn == cb) {
            #pragma unroll
            for (int mf = 0; mf < 4; mf++) {
                int row = wm * 64 + mf * 16 + (lane >> 2);
                #pragma unroll
                for (int nf = 0; nf < 4; nf++) {
                    int col = nf * 8 + (lane & 3) * 2;
                    stage[row * 33 + col]       = acc[mf][nf][0];
                    stage[row * 33 + col + 1]   = acc[mf][nf][1];
                    stage[(row + 8) * 33 + col]     = acc[mf][nf][2];
                    stage[(row + 8) * 33 + col + 1] = acc[mf][nf][3];
                }
            }
        }
        __syncthreads();
        #pragma unroll
        for (int i = 0; i < 4; i++) {
            int idx = tid + i * 256;
            int row = idx >> 3, q = idx & 7;
            if (m0 + row < M) {
                const float* r = stage + row * 33 + q * 4;
                *(float4*)&C[(size_t)(m0 + row) * N + n0 + cb * 32 + q * 4] =
                    make_float4(r[0], r[1], r[2], r[3]);
            }
        }
    }
    __syncthreads();
    if (tid < 128 && m0 + tid < M) {
        el[(size_t)(m0 + tid) * H + h] = el_s[tid];
        er[(size_t)(m0 + tid) * H + h] = er_s[tid];
    }
}

// ---------------- fused softmax + aggregation: one warp per (dst, head) ----------------
template <int H, bool ELU, bool SPLIT>
__global__ void k_agg(const float* __restrict__ f, const float* __restrict__ el,
                      const float* __restrict__ er, const float* __restrict__ b,
                      float* __restrict__ outF, __nv_bfloat16* __restrict__ outHi,
                      __nv_bfloat16* __restrict__ outLo) {
    int w = (blockIdx.x * blockDim.x + threadIdx.x) >> 5;
    int lane = threadIdx.x & 31;
    if (w >= NN * H) return;
    int d = w / H, h = w - d * H;
    int off0 = g_off[d];
    int deg = g_off[d + 1] - off0;
    float erd = er[d * H + h];

    float mx = -3.0e38f;
    for (int j = lane; j < deg; j += 32) {
        int s = g_csr_src[off0 + j];
        float v = el[s * H + h] + erd;
        v = v > 0.f ? v : NEG_SLOPE * v;
        mx = fmaxf(mx, v);
    }
    #pragma unroll
    for (int o = 16; o > 0; o >>= 1)
        mx = fmaxf(mx, __shfl_xor_sync(0xFFFFFFFFu, mx, o));

    float4 acc = make_float4(0.f, 0.f, 0.f, 0.f);
    float den = 0.f;
    for (int j = 0; j < deg; j++) {
        int s = g_csr_src[off0 + j];
        float v = el[s * H + h] + erd;
        v = v > 0.f ? v : NEG_SLOPE * v;
        float ex = __expf(v - mx);
        den += ex;
        float4 fv = *(const float4*)&f[(size_t)s * (H * DC) + h * DC + lane * 4];
        acc.x = fmaf(ex, fv.x, acc.x);
        acc.y = fmaf(ex, fv.y, acc.y);
        acc.z = fmaf(ex, fv.z, acc.z);
        acc.w = fmaf(ex, fv.w, acc.w);
    }
    float inv = 1.f / (den > 0.f ? den : 1.f);
    float4 bb = *(const float4*)&b[h * DC + lane * 4];
    float4 r;
    r.x = acc.x * inv + bb.x;
    r.y = acc.y * inv + bb.y;
    r.z = acc.z * inv + bb.z;
    r.w = acc.w * inv + bb.w;
    if (ELU) {
        r.x = r.x > 0.f ? r.x : expm1f(r.x);
        r.y = r.y > 0.f ? r.y : expm1f(r.y);
        r.z = r.z > 0.f ? r.z : expm1f(r.z);
        r.w = r.w > 0.f ? r.w : expm1f(r.w);
    }
    size_t base = (size_t)d * (H * DC) + h * DC + lane * 4;
    if (SPLIT) {
        __nv_bfloat16 h0 = __float2bfloat16(r.x), h1 = __float2bfloat16(r.y);
        __nv_bfloat16 h2 = __float2bfloat16(r.z), h3 = __float2bfloat16(r.w);
        __nv_bfloat16 l0 = __float2bfloat16(r.x - __bfloat162float(h0));
        __nv_bfloat16 l1 = __float2bfloat16(r.y - __bfloat162float(h1));
        __nv_bfloat16 l2 = __float2bfloat16(r.z - __bfloat162float(h2));
        __nv_bfloat16 l3 = __float2bfloat16(r.w - __bfloat162float(h3));
        *(__nv_bfloat162*)&outHi[base]     = __halves2bfloat162(h0, h1);
        *(__nv_bfloat162*)&outHi[base + 2] = __halves2bfloat162(h2, h3);
        *(__nv_bfloat162*)&outLo[base]     = __halves2bfloat162(l0, l1);
        *(__nv_bfloat162*)&outLo[base + 2] = __halves2bfloat162(l2, l3);
    } else {
        *(float4*)&outF[base] = r;
    }
}

// ---------------- graph mean pool (graph_ids sorted) ----------------
__global__ void k_pool(const float* __restrict__ h2, const int* __restrict__ gids) {
    __shared__ float sacc[NG][DC];
    __shared__ float scnt[NG];
    int tid = threadIdx.x;   // 128
    #pragma unroll
    for (int g = 0; g < NG; g++) sacc[g][tid] = 0.f;
    if (tid < NG) scnt[tid] = 0.f;
    __syncthreads();
    int per = (NN + gridDim.x - 1) / gridDim.x;
    int n0 = blockIdx.x * per;
    int n1 = n0 + per; if (n1 > NN) n1 = NN;
    int curg = -1; float racc = 0.f; float rcnt = 0.f;
    for (int n = n0; n < n1; n++) {
        int g = gids[n];
        if (g != curg) {
            if (curg >= 0) {
                sacc[curg][tid] += racc;
                if (tid == 0) scnt[curg] += rcnt;
            }
            curg = g; racc = 0.f; rcnt = 0.f;
        }
        racc += h2[(size_t)n * DC + tid];
        rcnt += 1.f;
    }
    if (curg >= 0) {
        sacc[curg][tid] += racc;
        if (tid == 0) scnt[curg] += rcnt;
    }
    __syncthreads();
    #pragma unroll
    for (int g = 0; g < NG; g++) atomicAdd(&g_sums[g * DC + tid], sacc[g][tid]);
    if (tid < NG) atomicAdd(&g_cnt[tid], scnt[tid]);
}

// ---------------- output: relu((sums/cnt) @ linW + linb) ----------------
__global__ void k_out(const float* __restrict__ linW, const float* __restrict__ linb,
                      float* __restrict__ out) {
    int g = blockIdx.x;
    int c = threadIdx.x;
    __shared__ float hg[DC];
    float cnt = g_cnt[g];
    if (cnt < 1.f) cnt = 1.f;
    hg[c] = g_sums[g * DC + c] / cnt;
    __syncthreads();
    float acc = linb[c];
    #pragma unroll 8
    for (int k = 0; k < DC; k++)
        acc = fmaf(hg[k], linW[k * DC + c], acc);
    out[g * DC + c] = acc > 0.f ? acc : 0.f;
}

// ---------------- launch ----------------
extern "C" void kernel_launch(void* const* d_in, const int* in_sizes, int n_in,
                              void* d_out, int out_size) {
    const float* x    = (const float*)d_in[0];
    const int*   src  = (const int*)  d_in[1];
    const int*   dst  = (const int*)  d_in[2];
    const int*   gids = (const int*)  d_in[3];
    const float* W1   = (const float*)d_in[4];
    const float* al1  = (const float*)d_in[5];
    const float* ar1  = (const float*)d_in[6];
    const float* b1   = (const float*)d_in[7];
    const float* W2   = (const float*)d_in[8];
    const float* al2  = (const float*)d_in[9];
    const float* ar2  = (const float*)d_in[10];
    const float* b2   = (const float*)d_in[11];
    const float* linW = (const float*)d_in[12];
    const float* linb = (const float*)d_in[13];
    float* out = (float*)d_out;

    void *p_f1, *p_el1, *p_er1, *p_xhi, *p_xlo, *p_hhi, *p_hlo;
    void *p_w1h, *p_w1l, *p_w2h, *p_w2l;
    void *p_f2, *p_el2, *p_er2, *p_h2;
    cudaGetSymbolAddress(&p_f1,  g_f1);
    cudaGetSymbolAddress(&p_el1, g_el1);
    cudaGetSymbolAddress(&p_er1, g_er1);
    cudaGetSymbolAddress(&p_xhi, g_xhi);
    cudaGetSymbolAddress(&p_xlo, g_xlo);
    cudaGetSymbolAddress(&p_hhi, g_hhi);
    cudaGetSymbolAddress(&p_hlo, g_hlo);
    cudaGetSymbolAddress(&p_w1h, g_w1t_hi);
    cudaGetSymbolAddress(&p_w1l, g_w1t_lo);
    cudaGetSymbolAddress(&p_w2h, g_w2t_hi);
    cudaGetSymbolAddress(&p_w2l, g_w2t_lo);
    cudaGetSymbolAddress(&p_f2,  g_f2);
    cudaGetSymbolAddress(&p_el2, g_el2);
    cudaGetSymbolAddress(&p_er2, g_er2);
    cudaGetSymbolAddress(&p_h2,  g_h2);

    // CSR build + prep
    k_zero_small<<<(NN + 255) / 256, 256>>>();
    k_deg<<<(NE + 255) / 256, 256>>>(dst);
    k_scan<<<1, 256>>>();
    k_scatter<<<(NE + 255) / 256, 256>>>(src, dst);
    k_split<<<(NN * DC / 4 + 255) / 256, 256>>>(x, (__nv_bfloat16*)p_xhi,
                                                (__nv_bfloat16*)p_xlo, NN * DC);
    k_tsplit<<<(F1C * DC + 255) / 256, 256>>>(W1, (__nv_bfloat16*)p_w1h,
                                              (__nv_bfloat16*)p_w1l, DC, F1C);
    k_tsplit<<<(DC * F1C + 255) / 256, 256>>>(W2, (__nv_bfloat16*)p_w2h,
                                              (__nv_bfloat16*)p_w2l, F1C, DC);

    int mtiles = (NN + 127) / 128;   // 157

    // ---- Layer 1: GEMM + fused scores ----
    {
        dim3 grid(F1C / 128, mtiles);
        k_gemm_mma<<<grid, 256, SM_GEMM>>>(
            (const __nv_bfloat16*)p_xhi, (const __nv_bfloat16*)p_xlo,
            (const __nv_bfloat16*)p_w1h, (const __nv_bfloat16*)p_w1l,
            (float*)p_f1, al1, ar1, (float*)p_el1, (float*)p_er1,
            NN, F1C, DC, H1C);
    }
    {
        int warps = NN * H1C;
        k_agg<H1C, true, true><<<(warps * 32 + 255) / 256, 256>>>(
            (const float*)p_f1, (const float*)p_el1, (const float*)p_er1, b1,
            nullptr, (__nv_bfloat16*)p_hhi, (__nv_bfloat16*)p_hlo);
    }

    // ---- Layer 2 ----
    {
        dim3 grid(1, mtiles);
        k_gemm_mma<<<grid, 256, SM_GEMM>>>(
            (const __nv_bfloat16*)p_hhi, (const __nv_bfloat16*)p_hlo,
            (const __nv_bfloat16*)p_w2h, (const __nv_bfloat16*)p_w2l,
            (float*)p_f2, al2, ar2, (float*)p_el2, (float*)p_er2,
            NN, DC, F1C, 1);
    }
    {
        int warps = NN;
        k_agg<1, false, false><<<(warps * 32 + 255) / 256, 256>>>(
            (const float*)p_f2, (const float*)p_el2, (const float*)p_er2, b2,
            (float*)p_h2, nullptr, nullptr);
    }

    // ---- pool + readout ----
    k_pool<<<64, DC>>>((const float*)p_h2, gids);
    k_out<<<NG, DC>>>(linW, linb, out);
}

// round 5
// speedup vs baseline: 3.9015x; 1.1451x over previous
#include <cuda_runtime.h>
#include <cuda_bf16.h>
#include <cstdint>

#define NN 20000
#define NE 320000
#define NG 16
#define H1C 3
#define DC 128
#define F1C (H1C*DC)   // 384
#define NEG_SLOPE 0.2f

// ---------------- scratch (device globals; no allocation) ----------------
__device__ float          g_f1[NN*F1C];
__device__ float          g_el1[NN*H1C];
__device__ float          g_er1[NN*H1C];
__device__ __nv_bfloat16  g_xhi[NN*DC];
__device__ __nv_bfloat16  g_xlo[NN*DC];
__device__ __nv_bfloat16  g_hhi[NN*F1C];
__device__ __nv_bfloat16  g_hlo[NN*F1C];
__device__ __nv_bfloat16  g_w1t_hi[F1C*DC];   // [384][128] = W1^T
__device__ __nv_bfloat16  g_w1t_lo[F1C*DC];
__device__ __nv_bfloat16  g_w2t_hi[DC*F1C];   // [128][384] = W2^T
__device__ __nv_bfloat16  g_w2t_lo[DC*F1C];
__device__ float          g_f2[NN*DC];
__device__ float          g_el2[NN];
__device__ float          g_er2[NN];
__device__ int            g_deg[NN];
__device__ int            g_cur[NN];
__device__ int            g_off[NN+1];
__device__ int            g_csr_src[NE];
__device__ float          g_sums[NG*DC];
__device__ float          g_cnt[NG];

// ---------------- helpers ----------------
__device__ __forceinline__ uint32_t smem_u32(const void* p) {
    uint32_t a;
    asm("{ .reg .u64 t; cvta.to.shared.u64 t, %1; cvt.u32.u64 %0, t; }" : "=r"(a) : "l"(p));
    return a;
}
__device__ __forceinline__ void mma16816(float* c, const uint32_t* a, const uint32_t* b) {
    asm volatile(
        "mma.sync.aligned.m16n8k16.row.col.f32.bf16.bf16.f32 "
        "{%0,%1,%2,%3}, {%4,%5,%6,%7}, {%8,%9}, {%0,%1,%2,%3};"
        : "+f"(c[0]), "+f"(c[1]), "+f"(c[2]), "+f"(c[3])
        : "r"(a[0]), "r"(a[1]), "r"(a[2]), "r"(a[3]), "r"(b[0]), "r"(b[1]));
}
__device__ __forceinline__ void ldsm4(uint32_t* d, uint32_t addr) {
    asm volatile("ldmatrix.sync.aligned.m8n8.x4.shared.b16 {%0,%1,%2,%3}, [%4];"
                 : "=r"(d[0]), "=r"(d[1]), "=r"(d[2]), "=r"(d[3]) : "r"(addr));
}
__device__ __forceinline__ void cp16(uint32_t saddr, const void* g) {
    asm volatile("cp.async.cg.shared.global [%0], [%1], 16;" :: "r"(saddr), "l"(g));
}
__device__ __forceinline__ void cp16p(uint32_t saddr, const void* g, int szbytes) {
    asm volatile("cp.async.cg.shared.global [%0], [%1], 16, %2;"
                 :: "r"(saddr), "l"(g), "r"(szbytes));
}

// smem layout for GEMM: two 40960B stages; within stage AHI=0, ALO=10240,
// BHI=20480, BLO=30720 (row stride 80B, 32 bf16 per row, 128 rows).
// el/er at 81920.  Epilogue C-stage reuses bytes [0, 16896).
#define STG 40960
#define S_ELER 81920
#define SM_GEMM (81920 + 1024)

// ---------------- small zero init ----------------
__global__ void k_zero_small() {
    int i = blockIdx.x * blockDim.x + threadIdx.x;
    if (i < NN) { g_deg[i] = 0; g_cur[i] = 0; }
    if (i < NG*DC) g_sums[i] = 0.f;
    if (i < NG) g_cnt[i] = 0.f;
}

// ---------------- CSR build (+ graph node counts) ----------------
__global__ void k_deg(const int* __restrict__ dst, const int* __restrict__ gids) {
    int i = blockIdx.x * blockDim.x + threadIdx.x;
    if (i < NE) atomicAdd(&g_deg[dst[i]], 1);
    if (i < NN) atomicAdd(&g_cnt[gids[i]], 1.f);
}
__global__ void k_scan() {
    __shared__ int partial[1024];
    int tid = threadIdx.x;
    const int CH = (NN + 1023) / 1024;   // 20
    int b0 = tid * CH;
    int s = 0;
    for (int i = 0; i < CH; i++) { int n = b0 + i; if (n < NN) s += g_deg[n]; }
    partial[tid] = s;
    __syncthreads();
    if (tid == 0) {
        int c = 0;
        for (int i = 0; i < 1024; i++) { int t = partial[i]; partial[i] = c; c += t; }
        g_off[NN] = c;
    }
    __syncthreads();
    int run = partial[tid];
    for (int i = 0; i < CH; i++) {
        int n = b0 + i;
        if (n < NN) { g_off[n] = run; run += g_deg[n]; }
    }
}
__global__ void k_scatter(const int* __restrict__ src, const int* __restrict__ dst) {
    int i = blockIdx.x * blockDim.x + threadIdx.x;
    if (i >= NE) return;
    int d = dst[i];
    int p = atomicAdd(&g_cur[d], 1);
    g_csr_src[g_off[d] + p] = src[i];
}

// ---------------- fp32 -> bf16 hi/lo split ----------------
__global__ void k_split(const float* __restrict__ A, __nv_bfloat16* __restrict__ hi,
                        __nv_bfloat16* __restrict__ lo, int n) {
    int i = 4 * (blockIdx.x * blockDim.x + threadIdx.x);
    if (i >= n) return;
    float4 v = *(const float4*)&A[i];
    __nv_bfloat16 h0 = __float2bfloat16(v.x), h1 = __float2bfloat16(v.y);
    __nv_bfloat16 h2 = __float2bfloat16(v.z), h3 = __float2bfloat16(v.w);
    __nv_bfloat16 l0 = __float2bfloat16(v.x - __bfloat162float(h0));
    __nv_bfloat16 l1 = __float2bfloat16(v.y - __bfloat162float(h1));
    __nv_bfloat16 l2 = __float2bfloat16(v.z - __bfloat162float(h2));
    __nv_bfloat16 l3 = __float2bfloat16(v.w - __bfloat162float(h3));
    *(__nv_bfloat162*)&hi[i]     = __halves2bfloat162(h0, h1);
    *(__nv_bfloat162*)&hi[i + 2] = __halves2bfloat162(h2, h3);
    *(__nv_bfloat162*)&lo[i]     = __halves2bfloat162(l0, l1);
    *(__nv_bfloat162*)&lo[i + 2] = __halves2bfloat162(l2, l3);
}

// ---------------- W [K,N] -> W^T [N,K] bf16 hi/lo ----------------
__global__ void k_tsplit(const float* __restrict__ W, __nv_bfloat16* __restrict__ hi,
                         __nv_bfloat16* __restrict__ lo, int K, int N) {
    int i = blockIdx.x * blockDim.x + threadIdx.x;
    if (i >= N * K) return;
    int n = i / K, k = i - n * K;
    float x = W[(size_t)k * N + n];
    __nv_bfloat16 h = __float2bfloat16(x);
    hi[i] = h;
    lo[i] = __float2bfloat16(x - __bfloat162float(h));
}

// ---------------- HMMA split-bf16 GEMM, cp.async double-buffered ----------------
// C[M,N] = A[M,K] @ B^T, B stored [N,K]. Block 128x128, BK=32, 8 warps (2Mx4N).
// Fused epilogue: el[n,h]=dot(C_row,al[h]), er likewise (h = blockIdx.x).
__global__ void __launch_bounds__(256, 1)
k_gemm_mma(const __nv_bfloat16* __restrict__ Ahi, const __nv_bfloat16* __restrict__ Alo,
           const __nv_bfloat16* __restrict__ Bhi, const __nv_bfloat16* __restrict__ Blo,
           float* __restrict__ C, const float* __restrict__ al, const float* __restrict__ ar,
           float* __restrict__ el, float* __restrict__ er, int M, int N, int K, int H) {
    extern __shared__ char smem[];
    uint32_t sb = smem_u32(smem);
    int tid = threadIdx.x;
    int wid = tid >> 5, lane = tid & 31;
    int wm = wid >> 2, wn = wid & 3;
    int m0 = blockIdx.y * 128, n0 = blockIdx.x * 128;
    int h = blockIdx.x;

    float acc[4][4][4];
    #pragma unroll
    for (int i = 0; i < 4; i++)
        #pragma unroll
        for (int j = 0; j < 4; j++)
            #pragma unroll
            for (int q = 0; q < 4; q++) acc[i][j][q] = 0.f;

    int a_row = wm * 64 + (lane & 15);
    int a_coff = (lane >> 4) * 16;
    int b_row = wn * 32 + (lane & 7) + ((lane >> 4) & 1) * 8;
    int b_coff = ((lane >> 3) & 1) * 16;

    int nch = K >> 5;

    auto issue = [&](int c) {
        uint32_t stb = sb + (uint32_t)(c & 1) * STG;
        int k0 = c << 5;
        #pragma unroll
        for (int i = 0; i < 2; i++) {
            int ch = tid + i * 256;
            int r = ch >> 2, q = ch & 3;
            uint32_t so = stb + r * 80 + q * 16;
            int gm = m0 + r;
            int ok = (gm < M) ? 16 : 0;
            int rs = ok ? gm : 0;
            cp16p(so,         &Ahi[(size_t)rs * K + k0 + q * 8], ok);
            cp16p(so + 10240, &Alo[(size_t)rs * K + k0 + q * 8], ok);
            cp16(so + 20480, &Bhi[(size_t)(n0 + r) * K + k0 + q * 8]);
            cp16(so + 30720, &Blo[(size_t)(n0 + r) * K + k0 + q * 8]);
        }
        asm volatile("cp.async.commit_group;" ::: "memory");
    };

    issue(0);
    for (int c = 0; c < nch; c++) {
        if (c + 1 < nch) {
            issue(c + 1);
            asm volatile("cp.async.wait_group 1;" ::: "memory");
        } else {
            asm volatile("cp.async.wait_group 0;" ::: "memory");
        }
        __syncthreads();
        uint32_t stb = sb + (uint32_t)(c & 1) * STG;
        #pragma unroll
        for (int ks = 0; ks < 2; ks++) {
            uint32_t kb = ks * 32;
            uint32_t ahi[4][4], alo[4][4];
            #pragma unroll
            for (int mf = 0; mf < 4; mf++) {
                uint32_t ao = (a_row + mf * 16) * 80 + kb + a_coff;
                ldsm4(ahi[mf], stb + 0 + ao);
                ldsm4(alo[mf], stb + 10240 + ao);
            }
            uint32_t bhi[4][4], blo[4][4];
            #pragma unroll
            for (int j = 0; j < 2; j++) {
                uint32_t bo = (b_row + j * 16) * 80 + kb + b_coff;
                ldsm4(bhi[j * 2], stb + 20480 + bo);
                ldsm4(blo[j * 2], stb + 30720 + bo);
            }
            #pragma unroll
            for (int mf = 0; mf < 4; mf++) {
                #pragma unroll
                for (int nf = 0; nf < 4; nf++) {
                    const uint32_t* bh = &bhi[(nf >> 1) * 2][(nf & 1) * 2];
                    const uint32_t* bl = &blo[(nf >> 1) * 2][(nf & 1) * 2];
                    mma16816(acc[mf][nf], ahi[mf], bh);
                    mma16816(acc[mf][nf], ahi[mf], bl);
                    mma16816(acc[mf][nf], alo[mf], bh);
                }
            }
        }
        __syncthreads();
    }

    // ---- fused el/er: accumulate per-row dot partials into smem ----
    float* el_s = (float*)(smem + S_ELER);
    float* er_s = el_s + 128;
    if (tid < 128) { el_s[tid] = 0.f; er_s[tid] = 0.f; }
    __syncthreads();
    {
        float a0[4], a1[4], r0[4], r1[4];
        #pragma unroll
        for (int nf = 0; nf < 4; nf++) {
            int gc = h * DC + wn * 32 + nf * 8 + (lane & 3) * 2;
            a0[nf] = al[gc]; a1[nf] = al[gc + 1];
            r0[nf] = ar[gc]; r1[nf] = ar[gc + 1];
        }
        #pragma unroll
        for (int mf = 0; mf < 4; mf++) {
            float s0e = 0.f, s0r = 0.f, s1e = 0.f, s1r = 0.f;
            #pragma unroll
            for (int nf = 0; nf < 4; nf++) {
                s0e += acc[mf][nf][0] * a0[nf] + acc[mf][nf][1] * a1[nf];
                s0r += acc[mf][nf][0] * r0[nf] + acc[mf][nf][1] * r1[nf];
                s1e += acc[mf][nf][2] * a0[nf] + acc[mf][nf][3] * a1[nf];
                s1r += acc[mf][nf][2] * r0[nf] + acc[mf][nf][3] * r1[nf];
            }
            int row = wm * 64 + mf * 16 + (lane >> 2);
            atomicAdd(&el_s[row], s0e);
            atomicAdd(&er_s[row], s0r);
            atomicAdd(&el_s[row + 8], s1e);
            atomicAdd(&er_s[row + 8], s1r);
        }
    }

    // ---- staged C store: 4 chunks of 32 cols ----
    float* stage = (float*)smem;   // [128][33]
    #pragma unroll
    for (int cb = 0; cb < 4; cb++) {
        __syncthreads();
        if (wn == cb) {
            #pragma unroll
            for (int mf = 0; mf < 4; mf++) {
                int row = wm * 64 + mf * 16 + (lane >> 2);
                #pragma unroll
                for (int nf = 0; nf < 4; nf++) {
                    int col = nf * 8 + (lane & 3) * 2;
                    stage[row * 33 + col]       = acc[mf][nf][0];
                    stage[row * 33 + col + 1]   = acc[mf][nf][1];
                    stage[(row + 8) * 33 + col]     = acc[mf][nf][2];
                    stage[(row + 8) * 33 + col + 1] = acc[mf][nf][3];
                }
            }
        }
        __syncthreads();
        #pragma unroll
        for (int i = 0; i < 4; i++) {
            int idx = tid + i * 256;
            int row = idx >> 3, q = idx & 7;
            if (m0 + row < M) {
                const float* r = stage + row * 33 + q * 4;
                *(float4*)&C[(size_t)(m0 + row) * N + n0 + cb * 32 + q * 4] =
                    make_float4(r[0], r[1], r[2], r[3]);
            }
        }
    }
    __syncthreads();
    if (tid < 128 && m0 + tid < M) {
        el[(size_t)(m0 + tid) * H + h] = el_s[tid];
        er[(size_t)(m0 + tid) * H + h] = er_s[tid];
    }
}

// ---------------- softmax+agg core (per-warp) ----------------
template <int H>
__device__ __forceinline__ void agg_core(const float* __restrict__ f,
                                         const float* __restrict__ el, float erd,
                                         int off0, int deg, int h, int lane,
                                         float4& r, float& den) {
    float mx = -3.0e38f;
    for (int j = lane; j < deg; j += 32) {
        int s = g_csr_src[off0 + j];
        float v = el[s * H + h] + erd;
        v = v > 0.f ? v : NEG_SLOPE * v;
        mx = fmaxf(mx, v);
    }
    #pragma unroll
    for (int o = 16; o > 0; o >>= 1)
        mx = fmaxf(mx, __shfl_xor_sync(0xFFFFFFFFu, mx, o));

    float4 acc = make_float4(0.f, 0.f, 0.f, 0.f);
    den = 0.f;
    int j = 0;
    for (; j + 2 <= deg; j += 2) {
        int s0 = g_csr_src[off0 + j];
        int s1 = g_csr_src[off0 + j + 1];
        float v0 = el[s0 * H + h] + erd;
        float v1 = el[s1 * H + h] + erd;
        v0 = v0 > 0.f ? v0 : NEG_SLOPE * v0;
        v1 = v1 > 0.f ? v1 : NEG_SLOPE * v1;
        float e0 = __expf(v0 - mx);
        float e1 = __expf(v1 - mx);
        float4 f0 = *(const float4*)&f[(size_t)s0 * (H * DC) + h * DC + lane * 4];
        float4 f1 = *(const float4*)&f[(size_t)s1 * (H * DC) + h * DC + lane * 4];
        den += e0 + e1;
        acc.x = fmaf(e0, f0.x, fmaf(e1, f1.x, acc.x));
        acc.y = fmaf(e0, f0.y, fmaf(e1, f1.y, acc.y));
        acc.z = fmaf(e0, f0.z, fmaf(e1, f1.z, acc.z));
        acc.w = fmaf(e0, f0.w, fmaf(e1, f1.w, acc.w));
    }
    if (j < deg) {
        int s0 = g_csr_src[off0 + j];
        float v0 = el[s0 * H + h] + erd;
        v0 = v0 > 0.f ? v0 : NEG_SLOPE * v0;
        float e0 = __expf(v0 - mx);
        float4 f0 = *(const float4*)&f[(size_t)s0 * (H * DC) + h * DC + lane * 4];
        den += e0;
        acc.x = fmaf(e0, f0.x, acc.x);
        acc.y = fmaf(e0, f0.y, acc.y);
        acc.z = fmaf(e0, f0.z, acc.z);
        acc.w = fmaf(e0, f0.w, acc.w);
    }
    r = acc;
}

// ---------------- layer-1 agg: elu + bf16 hi/lo split output ----------------
__global__ void k_agg1(const float* __restrict__ f, const float* __restrict__ el,
                       const float* __restrict__ er, const float* __restrict__ b,
                       __nv_bfloat16* __restrict__ outHi, __nv_bfloat16* __restrict__ outLo) {
    int w = (blockIdx.x * blockDim.x + threadIdx.x) >> 5;
    int lane = threadIdx.x & 31;
    if (w >= NN * H1C) return;
    int d = w / H1C, h = w - d * H1C;
    int off0 = g_off[d];
    int deg = g_off[d + 1] - off0;
    float erd = er[d * H1C + h];

    float4 acc; float den;
    agg_core<H1C>(f, el, erd, off0, deg, h, lane, acc, den);

    float inv = 1.f / (den > 0.f ? den : 1.f);
    float4 bb = *(const float4*)&b[h * DC + lane * 4];
    float4 r;
    r.x = acc.x * inv + bb.x;
    r.y = acc.y * inv + bb.y;
    r.z = acc.z * inv + bb.z;
    r.w = acc.w * inv + bb.w;
    r.x = r.x > 0.f ? r.x : expm1f(r.x);
    r.y = r.y > 0.f ? r.y : expm1f(r.y);
    r.z = r.z > 0.f ? r.z : expm1f(r.z);
    r.w = r.w > 0.f ? r.w : expm1f(r.w);

    size_t base = (size_t)d * F1C + h * DC + lane * 4;
    __nv_bfloat16 h0 = __float2bfloat16(r.x), h1 = __float2bfloat16(r.y);
    __nv_bfloat16 h2 = __float2bfloat16(r.z), h3 = __float2bfloat16(r.w);
    __nv_bfloat16 l0 = __float2bfloat16(r.x - __bfloat162float(h0));
    __nv_bfloat16 l1 = __float2bfloat16(r.y - __bfloat162float(h1));
    __nv_bfloat16 l2 = __float2bfloat16(r.z - __bfloat162float(h2));
    __nv_bfloat16 l3 = __float2bfloat16(r.w - __bfloat162float(h3));
    *(__nv_bfloat162*)&outHi[base]     = __halves2bfloat162(h0, h1);
    *(__nv_bfloat162*)&outHi[base + 2] = __halves2bfloat162(h2, h3);
    *(__nv_bfloat162*)&outLo[base]     = __halves2bfloat162(l0, l1);
    *(__nv_bfloat162*)&outLo[base + 2] = __halves2bfloat162(l2, l3);
}

// ---------------- layer-2 agg fused with graph mean-pool accumulation ----------------
// 8 warps/block, warp wid handles node d = blockIdx.x*8 + wid. NN % 8 == 0.
__global__ void k_agg_pool(const float* __restrict__ f, const float* __restrict__ el,
                           const float* __restrict__ er, const float* __restrict__ b,
                           const int* __restrict__ gids) {
    __shared__ float pacc[DC];
    __shared__ int uni;
    int tid = threadIdx.x;
    int wid = tid >> 5, lane = tid & 31;
    int d0 = blockIdx.x * 8;
    int d = d0 + wid;
    if (tid == 0) uni = (gids[d0] == gids[d0 + 7]) ? 1 : 0;
    if (tid < DC) pacc[tid] = 0.f;
    __syncthreads();

    int off0 = g_off[d];
    int deg = g_off[d + 1] - off0;
    float erd = er[d];

    float4 acc; float den;
    agg_core<1>(f, el, erd, off0, deg, 0, lane, acc, den);

    float inv = 1.f / (den > 0.f ? den : 1.f);
    float4 bb = *(const float4*)&b[lane * 4];
    float4 r;
    r.x = acc.x * inv + bb.x;
    r.y = acc.y * inv + bb.y;
    r.z = acc.z * inv + bb.z;
    r.w = acc.w * inv + bb.w;

    if (uni) {
        atomicAdd(&pacc[lane * 4 + 0], r.x);
        atomicAdd(&pacc[lane * 4 + 1], r.y);
        atomicAdd(&pacc[lane * 4 + 2], r.z);
        atomicAdd(&pacc[lane * 4 + 3], r.w);
    } else {
        int g = gids[d];
        atomicAdd(&g_sums[g * DC + lane * 4 + 0], r.x);
        atomicAdd(&g_sums[g * DC + lane * 4 + 1], r.y);
        atomicAdd(&g_sums[g * DC + lane * 4 + 2], r.z);
        atomicAdd(&g_sums[g * DC + lane * 4 + 3], r.w);
    }
    __syncthreads();
    if (uni && tid < DC) atomicAdd(&g_sums[gids[d0] * DC + tid], pacc[tid]);
}

// ---------------- output: relu((sums/cnt) @ linW + linb) ----------------
__global__ void k_out(const float* __restrict__ linW, const float* __restrict__ linb,
                      float* __restrict__ out) {
    int g = blockIdx.x;
    int c = threadIdx.x;
    __shared__ float hg[DC];
    float cnt = g_cnt[g];
    if (cnt < 1.f) cnt = 1.f;
    hg[c] = g_sums[g * DC + c] / cnt;
    __syncthreads();
    float acc = linb[c];
    #pragma unroll 8
    for (int k = 0; k < DC; k++)
        acc = fmaf(hg[k], linW[k * DC + c], acc);
    out[g * DC + c] = acc > 0.f ? acc : 0.f;
}

// ---------------- launch ----------------
extern "C" void kernel_launch(void* const* d_in, const int* in_sizes, int n_in,
                              void* d_out, int out_size) {
    const float* x    = (const float*)d_in[0];
    const int*   src  = (const int*)  d_in[1];
    const int*   dst  = (const int*)  d_in[2];
    const int*   gids = (const int*)  d_in[3];
    const float* W1   = (const float*)d_in[4];
    const float* al1  = (const float*)d_in[5];
    const float* ar1  = (const float*)d_in[6];
    const float* b1   = (const float*)d_in[7];
    const float* W2   = (const float*)d_in[8];
    const float* al2  = (const float*)d_in[9];
    const float* ar2  = (const float*)d_in[10];
    const float* b2   = (const float*)d_in[11];
    const float* linW = (const float*)d_in[12];
    const float* linb = (const float*)d_in[13];
    float* out = (float*)d_out;

    cudaFuncSetAttribute(k_gemm_mma, cudaFuncAttributeMaxDynamicSharedMemorySize, SM_GEMM);

    void *p_f1, *p_el1, *p_er1, *p_xhi, *p_xlo, *p_hhi, *p_hlo;
    void *p_w1h, *p_w1l, *p_w2h, *p_w2l;
    void *p_f2, *p_el2, *p_er2;
    cudaGetSymbolAddress(&p_f1,  g_f1);
    cudaGetSymbolAddress(&p_el1, g_el1);
    cudaGetSymbolAddress(&p_er1, g_er1);
    cudaGetSymbolAddress(&p_xhi, g_xhi);
    cudaGetSymbolAddress(&p_xlo, g_xlo);
    cudaGetSymbolAddress(&p_hhi, g_hhi);
    cudaGetSymbolAddress(&p_hlo, g_hlo);
    cudaGetSymbolAddress(&p_w1h, g_w1t_hi);
    cudaGetSymbolAddress(&p_w1l, g_w1t_lo);
    cudaGetSymbolAddress(&p_w2h, g_w2t_hi);
    cudaGetSymbolAddress(&p_w2l, g_w2t_lo);
    cudaGetSymbolAddress(&p_f2,  g_f2);
    cudaGetSymbolAddress(&p_el2, g_el2);
    cudaGetSymbolAddress(&p_er2, g_er2);

    // CSR build + prep
    k_zero_small<<<(NN + 255) / 256, 256>>>();
    k_deg<<<(NE + 255) / 256, 256>>>(dst, gids);
    k_scan<<<1, 1024>>>();
    k_scatter<<<(NE + 255) / 256, 256>>>(src, dst);
    k_split<<<(NN * DC / 4 + 255) / 256, 256>>>(x, (__nv_bfloat16*)p_xhi,
                                                (__nv_bfloat16*)p_xlo, NN * DC);
    k_tsplit<<<(F1C * DC + 255) / 256, 256>>>(W1, (__nv_bfloat16*)p_w1h,
                                              (__nv_bfloat16*)p_w1l, DC, F1C);
    k_tsplit<<<(DC * F1C + 255) / 256, 256>>>(W2, (__nv_bfloat16*)p_w2h,
                                              (__nv_bfloat16*)p_w2l, F1C, DC);

    int mtiles = (NN + 127) / 128;   // 157

    // ---- Layer 1: GEMM + fused scores ----
    {
        dim3 grid(F1C / 128, mtiles);
        k_gemm_mma<<<grid, 256, SM_GEMM>>>(
            (const __nv_bfloat16*)p_xhi, (const __nv_bfloat16*)p_xlo,
            (const __nv_bfloat16*)p_w1h, (const __nv_bfloat16*)p_w1l,
            (float*)p_f1, al1, ar1, (float*)p_el1, (float*)p_er1,
            NN, F1C, DC, H1C);
    }
    {
        int warps = NN * H1C;
        k_agg1<<<(warps * 32 + 255) / 256, 256>>>(
            (const float*)p_f1, (const float*)p_el1, (const float*)p_er1, b1,
            (__nv_bfloat16*)p_hhi, (__nv_bfloat16*)p_hlo);
    }

    // ---- Layer 2 ----
    {
        dim3 grid(1, mtiles);
        k_gemm_mma<<<grid, 256, SM_GEMM>>>(
            (const __nv_bfloat16*)p_hhi, (const __nv_bfloat16*)p_hlo,
            (const __nv_bfloat16*)p_w2h, (const __nv_bfloat16*)p_w2l,
            (float*)p_f2, al2, ar2, (float*)p_el2, (float*)p_er2,
            NN, DC, F1C, 1);
    }
    k_agg_pool<<<NN / 8, 256>>>((const float*)p_f2, (const float*)p_el2,
                                (const float*)p_er2, b2, gids);

    // ---- readout ----
    k_out<<<NG, DC>>>(linW, linb, out);
}

// round 6
// speedup vs baseline: 4.5404x; 1.1637x over previous
#include <cuda_runtime.h>
#include <cuda_bf16.h>
#include <cstdint>

#define NN 20000
#define NE 320000
#define NG 16
#define H1C 3
#define DC 128
#define F1C (H1C*DC)   // 384
#define NEG_SLOPE 0.2f

// ---------------- scratch (device globals; no allocation) ----------------
__device__ float          g_f1[NN*F1C];
__device__ float          g_el1[NN*H1C];
__device__ float          g_er1[NN*H1C];
__device__ __nv_bfloat16  g_xhi[NN*DC];
__device__ __nv_bfloat16  g_xlo[NN*DC];
__device__ __nv_bfloat16  g_hhi[NN*F1C];
__device__ __nv_bfloat16  g_hlo[NN*F1C];
__device__ __nv_bfloat16  g_w1t_hi[F1C*DC];   // [384][128] = W1^T
__device__ __nv_bfloat16  g_w1t_lo[F1C*DC];
__device__ __nv_bfloat16  g_w2t_hi[DC*F1C];   // [128][384] = W2^T
__device__ __nv_bfloat16  g_w2t_lo[DC*F1C];
__device__ float          g_f2[NN*DC];
__device__ float          g_el2[NN];
__device__ float          g_er2[NN];
__device__ int            g_deg[NN];
__device__ int            g_cur[NN];
__device__ int            g_off[NN+1];
__device__ int            g_csr_src[NE];
__device__ float          g_sums[NG*DC];
__device__ float          g_cnt[NG];

// ---------------- helpers ----------------
__device__ __forceinline__ uint32_t smem_u32(const void* p) {
    uint32_t a;
    asm("{ .reg .u64 t; cvta.to.shared.u64 t, %1; cvt.u32.u64 %0, t; }" : "=r"(a) : "l"(p));
    return a;
}
__device__ __forceinline__ void mma16816(float* c, const uint32_t* a, const uint32_t* b) {
    asm volatile(
        "mma.sync.aligned.m16n8k16.row.col.f32.bf16.bf16.f32 "
        "{%0,%1,%2,%3}, {%4,%5,%6,%7}, {%8,%9}, {%0,%1,%2,%3};"
        : "+f"(c[0]), "+f"(c[1]), "+f"(c[2]), "+f"(c[3])
        : "r"(a[0]), "r"(a[1]), "r"(a[2]), "r"(a[3]), "r"(b[0]), "r"(b[1]));
}
__device__ __forceinline__ void ldsm4(uint32_t* d, uint32_t addr) {
    asm volatile("ldmatrix.sync.aligned.m8n8.x4.shared.b16 {%0,%1,%2,%3}, [%4];"
                 : "=r"(d[0]), "=r"(d[1]), "=r"(d[2]), "=r"(d[3]) : "r"(addr));
}
__device__ __forceinline__ void cp16(uint32_t saddr, const void* g) {
    asm volatile("cp.async.cg.shared.global [%0], [%1], 16;" :: "r"(saddr), "l"(g));
}
__device__ __forceinline__ void cp16p(uint32_t saddr, const void* g, int szbytes) {
    asm volatile("cp.async.cg.shared.global [%0], [%1], 16, %2;"
                 :: "r"(saddr), "l"(g), "r"(szbytes));
}

// smem layout for GEMM: two 40960B stages; el/er at 81920.
#define STG 40960
#define S_ELER 81920
#define SM_GEMM (81920 + 1024)

// ---------------- small zero init ----------------
__global__ void k_zero_small() {
    int i = blockIdx.x * blockDim.x + threadIdx.x;
    if (i < NN) { g_deg[i] = 0; g_cur[i] = 0; }
    if (i < NG*DC) g_sums[i] = 0.f;
    if (i < NG) g_cnt[i] = 0.f;
}

// ---------------- CSR build (+ graph node counts) ----------------
__global__ void k_deg(const int* __restrict__ dst, const int* __restrict__ gids) {
    int i = blockIdx.x * blockDim.x + threadIdx.x;
    if (i < NE) atomicAdd(&g_deg[dst[i]], 1);
    if (i < NN) atomicAdd(&g_cnt[gids[i]], 1.f);
}
__global__ void k_scan() {
    __shared__ int partial[1024];
    int tid = threadIdx.x;
    const int CH = (NN + 1023) / 1024;   // 20
    int b0 = tid * CH;
    int s = 0;
    for (int i = 0; i < CH; i++) { int n = b0 + i; if (n < NN) s += g_deg[n]; }
    partial[tid] = s;
    __syncthreads();
    // warp-level scan of 1024 partials
    if (tid == 0) {
        int c = 0;
        for (int i = 0; i < 1024; i++) { int t = partial[i]; partial[i] = c; c += t; }
        g_off[NN] = c;
    }
    __syncthreads();
    int run = partial[tid];
    for (int i = 0; i < CH; i++) {
        int n = b0 + i;
        if (n < NN) { g_off[n] = run; run += g_deg[n]; }
    }
}
__global__ void k_scatter(const int* __restrict__ src, const int* __restrict__ dst) {
    int i = blockIdx.x * blockDim.x + threadIdx.x;
    if (i >= NE) return;
    int d = dst[i];
    int p = atomicAdd(&g_cur[d], 1);
    g_csr_src[g_off[d] + p] = src[i];
}

// ---------------- fp32 -> bf16 hi/lo split ----------------
__global__ void k_split(const float* __restrict__ A, __nv_bfloat16* __restrict__ hi,
                        __nv_bfloat16* __restrict__ lo, int n) {
    int i = 4 * (blockIdx.x * blockDim.x + threadIdx.x);
    if (i >= n) return;
    float4 v = *(const float4*)&A[i];
    __nv_bfloat16 h0 = __float2bfloat16(v.x), h1 = __float2bfloat16(v.y);
    __nv_bfloat16 h2 = __float2bfloat16(v.z), h3 = __float2bfloat16(v.w);
    __nv_bfloat16 l0 = __float2bfloat16(v.x - __bfloat162float(h0));
    __nv_bfloat16 l1 = __float2bfloat16(v.y - __bfloat162float(h1));
    __nv_bfloat16 l2 = __float2bfloat16(v.z - __bfloat162float(h2));
    __nv_bfloat16 l3 = __float2bfloat16(v.w - __bfloat162float(h3));
    *(__nv_bfloat162*)&hi[i]     = __halves2bfloat162(h0, h1);
    *(__nv_bfloat162*)&hi[i + 2] = __halves2bfloat162(h2, h3);
    *(__nv_bfloat162*)&lo[i]     = __halves2bfloat162(l0, l1);
    *(__nv_bfloat162*)&lo[i + 2] = __halves2bfloat162(l2, l3);
}

// ---------------- W [K,N] -> W^T [N,K] bf16 hi/lo ----------------
__global__ void k_tsplit(const float* __restrict__ W, __nv_bfloat16* __restrict__ hi,
                         __nv_bfloat16* __restrict__ lo, int K, int N) {
    int i = blockIdx.x * blockDim.x + threadIdx.x;
    if (i >= N * K) return;
    int n = i / K, k = i - n * K;
    float x = W[(size_t)k * N + n];
    __nv_bfloat16 h = __float2bfloat16(x);
    hi[i] = h;
    lo[i] = __float2bfloat16(x - __bfloat162float(h));
}

// ---------------- HMMA split-bf16 GEMM, cp.async double-buffered ----------------
__global__ void __launch_bounds__(256, 1)
k_gemm_mma(const __nv_bfloat16* __restrict__ Ahi, const __nv_bfloat16* __restrict__ Alo,
           const __nv_bfloat16* __restrict__ Bhi, const __nv_bfloat16* __restrict__ Blo,
           float* __restrict__ C, const float* __restrict__ al, const float* __restrict__ ar,
           float* __restrict__ el, float* __restrict__ er, int M, int N, int K, int H) {
    extern __shared__ char smem[];
    uint32_t sb = smem_u32(smem);
    int tid = threadIdx.x;
    int wid = tid >> 5, lane = tid & 31;
    int wm = wid >> 2, wn = wid & 3;
    int m0 = blockIdx.y * 128, n0 = blockIdx.x * 128;
    int h = blockIdx.x;

    float acc[4][4][4];
    #pragma unroll
    for (int i = 0; i < 4; i++)
        #pragma unroll
        for (int j = 0; j < 4; j++)
            #pragma unroll
            for (int q = 0; q < 4; q++) acc[i][j][q] = 0.f;

    int a_row = wm * 64 + (lane & 15);
    int a_coff = (lane >> 4) * 16;
    int b_row = wn * 32 + (lane & 7) + ((lane >> 4) & 1) * 8;
    int b_coff = ((lane >> 3) & 1) * 16;

    int nch = K >> 5;

    auto issue = [&](int c) {
        uint32_t stb = sb + (uint32_t)(c & 1) * STG;
        int k0 = c << 5;
        #pragma unroll
        for (int i = 0; i < 2; i++) {
            int ch = tid + i * 256;
            int r = ch >> 2, q = ch & 3;
            uint32_t so = stb + r * 80 + q * 16;
            int gm = m0 + r;
            int ok = (gm < M) ? 16 : 0;
            int rs = ok ? gm : 0;
            cp16p(so,         &Ahi[(size_t)rs * K + k0 + q * 8], ok);
            cp16p(so + 10240, &Alo[(size_t)rs * K + k0 + q * 8], ok);
            cp16(so + 20480, &Bhi[(size_t)(n0 + r) * K + k0 + q * 8]);
            cp16(so + 30720, &Blo[(size_t)(n0 + r) * K + k0 + q * 8]);
        }
        asm volatile("cp.async.commit_group;" ::: "memory");
    };

    issue(0);
    for (int c = 0; c < nch; c++) {
        if (c + 1 < nch) {
            issue(c + 1);
            asm volatile("cp.async.wait_group 1;" ::: "memory");
        } else {
            asm volatile("cp.async.wait_group 0;" ::: "memory");
        }
        __syncthreads();
        uint32_t stb = sb + (uint32_t)(c & 1) * STG;
        #pragma unroll
        for (int ks = 0; ks < 2; ks++) {
            uint32_t kb = ks * 32;
            uint32_t ahi[4][4], alo[4][4];
            #pragma unroll
            for (int mf = 0; mf < 4; mf++) {
                uint32_t ao = (a_row + mf * 16) * 80 + kb + a_coff;
                ldsm4(ahi[mf], stb + 0 + ao);
                ldsm4(alo[mf], stb + 10240 + ao);
            }
            uint32_t bhi[4][4], blo[4][4];
            #pragma unroll
            for (int j = 0; j < 2; j++) {
                uint32_t bo = (b_row + j * 16) * 80 + kb + b_coff;
                ldsm4(bhi[j * 2], stb + 20480 + bo);
                ldsm4(blo[j * 2], stb + 30720 + bo);
            }
            #pragma unroll
            for (int mf = 0; mf < 4; mf++) {
                #pragma unroll
                for (int nf = 0; nf < 4; nf++) {
                    const uint32_t* bh = &bhi[(nf >> 1) * 2][(nf & 1) * 2];
                    const uint32_t* bl = &blo[(nf >> 1) * 2][(nf & 1) * 2];
                    mma16816(acc[mf][nf], ahi[mf], bh);
                    mma16816(acc[mf][nf], ahi[mf], bl);
                    mma16816(acc[mf][nf], alo[mf], bh);
                }
            }
        }
        __syncthreads();
    }

    // ---- fused el/er ----
    float* el_s = (float*)(smem + S_ELER);
    float* er_s = el_s + 128;
    if (tid < 128) { el_s[tid] = 0.f; er_s[tid] = 0.f; }
    __syncthreads();
    {
        float a0[4], a1[4], r0[4], r1[4];
        #pragma unroll
        for (int nf = 0; nf < 4; nf++) {
            int gc = h * DC + wn * 32 + nf * 8 + (lane & 3) * 2;
            a0[nf] = al[gc]; a1[nf] = al[gc + 1];
            r0[nf] = ar[gc]; r1[nf] = ar[gc + 1];
        }
        #pragma unroll
        for (int mf = 0; mf < 4; mf++) {
            float s0e = 0.f, s0r = 0.f, s1e = 0.f, s1r = 0.f;
            #pragma unroll
            for (int nf = 0; nf < 4; nf++) {
                s0e += acc[mf][nf][0] * a0[nf] + acc[mf][nf][1] * a1[nf];
                s0r += acc[mf][nf][0] * r0[nf] + acc[mf][nf][1] * r1[nf];
                s1e += acc[mf][nf][2] * a0[nf] + acc[mf][nf][3] * a1[nf];
                s1r += acc[mf][nf][2] * r0[nf] + acc[mf][nf][3] * r1[nf];
            }
            int row = wm * 64 + mf * 16 + (lane >> 2);
            atomicAdd(&el_s[row], s0e);
            atomicAdd(&er_s[row], s0r);
            atomicAdd(&el_s[row + 8], s1e);
            atomicAdd(&er_s[row + 8], s1r);
        }
    }

    // ---- staged C store ----
    float* stage = (float*)smem;   // [128][33]
    #pragma unroll
    for (int cb = 0; cb < 4; cb++) {
        __syncthreads();
        if (wn == cb) {
            #pragma unroll
            for (int mf = 0; mf < 4; mf++) {
                int row = wm * 64 + mf * 16 + (lane >> 2);
                #pragma unroll
                for (int nf = 0; nf < 4; nf++) {
                    int col = nf * 8 + (lane & 3) * 2;
                    stage[row * 33 + col]       = acc[mf][nf][0];
                    stage[row * 33 + col + 1]   = acc[mf][nf][1];
                    stage[(row + 8) * 33 + col]     = acc[mf][nf][2];
                    stage[(row + 8) * 33 + col + 1] = acc[mf][nf][3];
                }
            }
        }
        __syncthreads();
        #pragma unroll
        for (int i = 0; i < 4; i++) {
            int idx = tid + i * 256;
            int row = idx >> 3, q = idx & 7;
            if (m0 + row < M) {
                const float* r = stage + row * 33 + q * 4;
                *(float4*)&C[(size_t)(m0 + row) * N + n0 + cb * 32 + q * 4] =
                    make_float4(r[0], r[1], r[2], r[3]);
            }
        }
    }
    __syncthreads();
    if (tid < 128 && m0 + tid < M) {
        el[(size_t)(m0 + tid) * H + h] = el_s[tid];
        er[(size_t)(m0 + tid) * H + h] = er_s[tid];
    }
}

// ---------------- softmax+agg core: register-resident softmax ----------------
template <int H>
__device__ __forceinline__ void agg_core(const float* __restrict__ f,
                                         const float* __restrict__ el, float erd,
                                         int off0, int deg, int h, int lane,
                                         float4& racc, float& den) {
    float4 acc = make_float4(0.f, 0.f, 0.f, 0.f);
    den = 0.f;
    if (deg <= 32) {
        // lane j owns edge j: one coalesced csr load + one parallel el gather
        int s = 0;
        float v = -3.0e38f;
        if (lane < deg) {
            s = g_csr_src[off0 + lane];
            v = el[s * H + h] + erd;
            v = v > 0.f ? v : NEG_SLOPE * v;
        }
        float mx = v;
        #pragma unroll
        for (int o = 16; o > 0; o >>= 1)
            mx = fmaxf(mx, __shfl_xor_sync(0xFFFFFFFFu, mx, o));
        float ex = (lane < deg) ? __expf(v - mx) : 0.f;
        float d = ex;
        #pragma unroll
        for (int o = 16; o > 0; o >>= 1)
            d += __shfl_xor_sync(0xFFFFFFFFu, d, o);
        den = d;
        #pragma unroll 4
        for (int j = 0; j < deg; j++) {
            float exj = __shfl_sync(0xFFFFFFFFu, ex, j);
            int   sj  = __shfl_sync(0xFFFFFFFFu, s, j);
            float4 fv = *(const float4*)&f[(size_t)sj * (H * DC) + h * DC + lane * 4];
            acc.x = fmaf(exj, fv.x, acc.x);
            acc.y = fmaf(exj, fv.y, acc.y);
            acc.z = fmaf(exj, fv.z, acc.z);
            acc.w = fmaf(exj, fv.w, acc.w);
        }
    } else {
        // rare fallback: two-pass
        float mx = -3.0e38f;
        for (int j = lane; j < deg; j += 32) {
            int s = g_csr_src[off0 + j];
            float v = el[s * H + h] + erd;
            v = v > 0.f ? v : NEG_SLOPE * v;
            mx = fmaxf(mx, v);
        }
        #pragma unroll
        for (int o = 16; o > 0; o >>= 1)
            mx = fmaxf(mx, __shfl_xor_sync(0xFFFFFFFFu, mx, o));
        for (int j = 0; j < deg; j++) {
            int s = g_csr_src[off0 + j];
            float v = el[s * H + h] + erd;
            v = v > 0.f ? v : NEG_SLOPE * v;
            float ex = __expf(v - mx);
            den += ex;
            float4 fv = *(const float4*)&f[(size_t)s * (H * DC) + h * DC + lane * 4];
            acc.x = fmaf(ex, fv.x, acc.x);
            acc.y = fmaf(ex, fv.y, acc.y);
            acc.z = fmaf(ex, fv.z, acc.z);
            acc.w = fmaf(ex, fv.w, acc.w);
        }
    }
    racc = acc;
}

// ---------------- layer-1 agg: elu + bf16 hi/lo split output ----------------
__global__ void k_agg1(const float* __restrict__ f, const float* __restrict__ el,
                       const float* __restrict__ er, const float* __restrict__ b,
                       __nv_bfloat16* __restrict__ outHi, __nv_bfloat16* __restrict__ outLo) {
    int w = (blockIdx.x * blockDim.x + threadIdx.x) >> 5;
    int lane = threadIdx.x & 31;
    if (w >= NN * H1C) return;
    int d = w / H1C, h = w - d * H1C;
    int off0 = g_off[d];
    int deg = g_off[d + 1] - off0;
    float erd = er[d * H1C + h];

    float4 acc; float den;
    agg_core<H1C>(f, el, erd, off0, deg, h, lane, acc, den);

    float inv = 1.f / (den > 0.f ? den : 1.f);
    float4 bb = *(const float4*)&b[h * DC + lane * 4];
    float4 r;
    r.x = acc.x * inv + bb.x;
    r.y = acc.y * inv + bb.y;
    r.z = acc.z * inv + bb.z;
    r.w = acc.w * inv + bb.w;
    r.x = r.x > 0.f ? r.x : expm1f(r.x);
    r.y = r.y > 0.f ? r.y : expm1f(r.y);
    r.z = r.z > 0.f ? r.z : expm1f(r.z);
    r.w = r.w > 0.f ? r.w : expm1f(r.w);

    size_t base = (size_t)d * F1C + h * DC + lane * 4;
    __nv_bfloat16 h0 = __float2bfloat16(r.x), h1 = __float2bfloat16(r.y);
    __nv_bfloat16 h2 = __float2bfloat16(r.z), h3 = __float2bfloat16(r.w);
    __nv_bfloat16 l0 = __float2bfloat16(r.x - __bfloat162float(h0));
    __nv_bfloat16 l1 = __float2bfloat16(r.y - __bfloat162float(h1));
    __nv_bfloat16 l2 = __float2bfloat16(r.z - __bfloat162float(h2));
    __nv_bfloat16 l3 = __float2bfloat16(r.w - __bfloat162float(h3));
    *(__nv_bfloat162*)&outHi[base]     = __halves2bfloat162(h0, h1);
    *(__nv_bfloat162*)&outHi[base + 2] = __halves2bfloat162(h2, h3);
    *(__nv_bfloat162*)&outLo[base]     = __halves2bfloat162(l0, l1);
    *(__nv_bfloat162*)&outLo[base + 2] = __halves2bfloat162(l2, l3);
}

// ---------------- layer-2 agg fused with graph mean-pool accumulation ----------------
__global__ void k_agg_pool(const float* __restrict__ f, const float* __restrict__ el,
                           const float* __restrict__ er, const float* __restrict__ b,
                           const int* __restrict__ gids) {
    __shared__ float pacc[DC];
    __shared__ int uni;
    int tid = threadIdx.x;
    int wid = tid >> 5, lane = tid & 31;
    int d0 = blockIdx.x * 8;
    int d = d0 + wid;
    if (tid == 0) uni = (gids[d0] == gids[d0 + 7]) ? 1 : 0;
    if (tid < DC) pacc[tid] = 0.f;
    __syncthreads();

    int off0 = g_off[d];
    int deg = g_off[d + 1] - off0;
    float erd = er[d];

    float4 acc; float den;
    agg_core<1>(f, el, erd, off0, deg, 0, lane, acc, den);

    float inv = 1.f / (den > 0.f ? den : 1.f);
    float4 bb = *(const float4*)&b[lane * 4];
    float4 r;
    r.x = acc.x * inv + bb.x;
    r.y = acc.y * inv + bb.y;
    r.z = acc.z * inv + bb.z;
    r.w = acc.w * inv + bb.w;

    if (uni) {
        atomicAdd(&pacc[lane * 4 + 0], r.x);
        atomicAdd(&pacc[lane * 4 + 1], r.y);
        atomicAdd(&pacc[lane * 4 + 2], r.z);
        atomicAdd(&pacc[lane * 4 + 3], r.w);
    } else {
        int g = gids[d];
        atomicAdd(&g_sums[g * DC + lane * 4 + 0], r.x);
        atomicAdd(&g_sums[g * DC + lane * 4 + 1], r.y);
        atomicAdd(&g_sums[g * DC + lane * 4 + 2], r.z);
        atomicAdd(&g_sums[g * DC + lane * 4 + 3], r.w);
    }
    __syncthreads();
    if (uni && tid < DC) atomicAdd(&g_sums[gids[d0] * DC + tid], pacc[tid]);
}

// ---------------- output: relu((sums/cnt) @ linW + linb) ----------------
__global__ void k_out(const float* __restrict__ linW, const float* __restrict__ linb,
                      float* __restrict__ out) {
    int g = blockIdx.x;
    int c = threadIdx.x;
    __shared__ float hg[DC];
    float cnt = g_cnt[g];
    if (cnt < 1.f) cnt = 1.f;
    hg[c] = g_sums[g * DC + c] / cnt;
    __syncthreads();
    float acc = linb[c];
    #pragma unroll 8
    for (int k = 0; k < DC; k++)
        acc = fmaf(hg[k], linW[k * DC + c], acc);
    out[g * DC + c] = acc > 0.f ? acc : 0.f;
}

// ---------------- launch ----------------
extern "C" void kernel_launch(void* const* d_in, const int* in_sizes, int n_in,
                              void* d_out, int out_size) {
    const float* x    = (const float*)d_in[0];
    const int*   src  = (const int*)  d_in[1];
    const int*   dst  = (const int*)  d_in[2];
    const int*   gids = (const int*)  d_in[3];
    const float* W1   = (const float*)d_in[4];
    const float* al1  = (const float*)d_in[5];
    const float* ar1  = (const float*)d_in[6];
    const float* b1   = (const float*)d_in[7];
    const float* W2   = (const float*)d_in[8];
    const float* al2  = (const float*)d_in[9];
    const float* ar2  = (const float*)d_in[10];
    const float* b2   = (const float*)d_in[11];
    const float* linW = (const float*)d_in[12];
    const float* linb = (const float*)d_in[13];
    float* out = (float*)d_out;

    static cudaStream_t s1 = nullptr;
    static cudaEvent_t evFork = nullptr, evJoin = nullptr;
    if (!s1) {
        cudaStreamCreateWithFlags(&s1, cudaStreamNonBlocking);
        cudaEventCreateWithFlags(&evFork, cudaEventDisableTiming);
        cudaEventCreateWithFlags(&evJoin, cudaEventDisableTiming);
        cudaFuncSetAttribute(k_gemm_mma, cudaFuncAttributeMaxDynamicSharedMemorySize, SM_GEMM);
    }

    void *p_f1, *p_el1, *p_er1, *p_xhi, *p_xlo, *p_hhi, *p_hlo;
    void *p_w1h, *p_w1l, *p_w2h, *p_w2l;
    void *p_f2, *p_el2, *p_er2;
    cudaGetSymbolAddress(&p_f1,  g_f1);
    cudaGetSymbolAddress(&p_el1, g_el1);
    cudaGetSymbolAddress(&p_er1, g_er1);
    cudaGetSymbolAddress(&p_xhi, g_xhi);
    cudaGetSymbolAddress(&p_xlo, g_xlo);
    cudaGetSymbolAddress(&p_hhi, g_hhi);
    cudaGetSymbolAddress(&p_hlo, g_hlo);
    cudaGetSymbolAddress(&p_w1h, g_w1t_hi);
    cudaGetSymbolAddress(&p_w1l, g_w1t_lo);
    cudaGetSymbolAddress(&p_w2h, g_w2t_hi);
    cudaGetSymbolAddress(&p_w2l, g_w2t_lo);
    cudaGetSymbolAddress(&p_f2,  g_f2);
    cudaGetSymbolAddress(&p_el2, g_el2);
    cudaGetSymbolAddress(&p_er2, g_er2);

    // ---- fork: CSR branch on s1, GEMM-prep branch on stream 0 ----
    cudaEventRecord(evFork, 0);
    cudaStreamWaitEvent(s1, evFork, 0);

    // Branch A (s1): CSR build + pool-count init
    k_zero_small<<<(NN + 255) / 256, 256, 0, s1>>>();
    k_deg<<<(NE + 255) / 256, 256, 0, s1>>>(dst, gids);
    k_scan<<<1, 1024, 0, s1>>>();
    k_scatter<<<(NE + 255) / 256, 256, 0, s1>>>(src, dst);
    cudaEventRecord(evJoin, s1);

    // Branch B (stream 0): splits + GEMM1
    k_split<<<(NN * DC / 4 + 255) / 256, 256>>>(x, (__nv_bfloat16*)p_xhi,
                                                (__nv_bfloat16*)p_xlo, NN * DC);
    k_tsplit<<<(F1C * DC + 255) / 256, 256>>>(W1, (__nv_bfloat16*)p_w1h,
                                              (__nv_bfloat16*)p_w1l, DC, F1C);
    k_tsplit<<<(DC * F1C + 255) / 256, 256>>>(W2, (__nv_bfloat16*)p_w2h,
                                              (__nv_bfloat16*)p_w2l, F1C, DC);

    int mtiles = (NN + 127) / 128;   // 157
    {
        dim3 grid(F1C / 128, mtiles);
        k_gemm_mma<<<grid, 256, SM_GEMM>>>(
            (const __nv_bfloat16*)p_xhi, (const __nv_bfloat16*)p_xlo,
            (const __nv_bfloat16*)p_w1h, (const __nv_bfloat16*)p_w1l,
            (float*)p_f1, al1, ar1, (float*)p_el1, (float*)p_er1,
            NN, F1C, DC, H1C);
    }

    // ---- join: agg1 needs CSR + GEMM1 ----
    cudaStreamWaitEvent(0, evJoin, 0);
    {
        int warps = NN * H1C;
        k_agg1<<<(warps * 32 + 255) / 256, 256>>>(
            (const float*)p_f1, (const float*)p_el1, (const float*)p_er1, b1,
            (__nv_bfloat16*)p_hhi, (__nv_bfloat16*)p_hlo);
    }

    // ---- Layer 2 ----
    {
        dim3 grid(1, mtiles);
        k_gemm_mma<<<grid, 256, SM_GEMM>>>(
            (const __nv_bfloat16*)p_hhi, (const __nv_bfloat16*)p_hlo,
            (const __nv_bfloat16*)p_w2h, (const __nv_bfloat16*)p_w2l,
            (float*)p_f2, al2, ar2, (float*)p_el2, (float*)p_er2,
            NN, DC, F1C, 1);
    }
    k_agg_pool<<<NN / 8, 256>>>((const float*)p_f2, (const float*)p_el2,
                                (const float*)p_er2, b2, gids);

    // ---- readout ----
    k_out<<<NG, DC>>>(linW, linb, out);
}